// round 8
// baseline (speedup 1.0000x reference)
#include <cuda_runtime.h>

// Swin shifted-window MSA: B=32, H=W=112, C=96, ws=7, ss=3, nh=3, hd=32
// Round 6: feed the FFMA2 pipe.
//  - weights pre-duplicated as f32x2 pairs in smem (no splat MOVs in inner loop)
//  - 2 windows per 256-thread block in k_qkv/k_proj (weight fills + barriers
//    amortized, occupancy 37.5% -> 50%)
//  - K processed in 12-row slices to stay under the 48KB static smem limit

#define WS_ 7
#define SS_ 3
#define NH_ 3
#define HD_ 32
#define C_  96
#define N_  49
#define HW_ 112
#define BNW 8192   // 32 * 16 * 16 windows

typedef unsigned long long ull;

// scratch (static device globals; no allocation in kernel_launch)
__device__ float g_qkv[(size_t)BNW * 3 * 3 * N_ * HD_]; // [win][head][which][n][d]
__device__ float g_y[(size_t)BNW * N_ * C_];            // [win][n][c]

__device__ __forceinline__ int rcode(int h) {
    return h < (HW_ - WS_) ? 0 : (h < (HW_ - SS_) ? 1 : 2);
}

// ---- packed f32x2 helpers ------------------------------------------------
__device__ __forceinline__ ull splat2(float v) {
    ull r; asm("mov.b64 %0, {%1, %1};" : "=l"(r) : "f"(v)); return r;
}
__device__ __forceinline__ void ffma2(ull& d, ull a, ull b) {
    asm("fma.rn.f32x2 %0, %1, %2, %0;" : "+l"(d) : "l"(a), "l"(b));
}
__device__ __forceinline__ float2 unpack2(ull v) {
    float2 r; asm("mov.b64 {%0, %1}, %2;" : "=f"(r.x), "=f"(r.y) : "l"(v)); return r;
}

// ---------------------------------------------------------------------------
// Kernel 1: QKV projection. grid = BNW/2, block = 256 (2 windows per block).
// ---------------------------------------------------------------------------
__global__ __launch_bounds__(256) void k_qkv(
    const float* __restrict__ x,
    const float* __restrict__ qkv_w,
    const float* __restrict__ qkv_b)
{
    __shared__ __align__(16) float xsT[2][C_][50]; // transposed windows [g][k][n]
    __shared__ __align__(16) ull   wtd[12][C_];    // 12-row K-slice, pair-duplicated

    const int tid = threadIdx.x;
    const int g   = tid >> 7;        // window sub-index within block
    const int t   = tid & 127;       // thread within group
    const int bw  = blockIdx.x * 2 + g;
    const int b   = bw >> 8;
    const int w   = bw & 255;
    const int wy  = w >> 4, wx = w & 15;

    // gather rolled window (transposed into smem), each 128-group does its own
    for (int u = t; u < N_ * 24; u += 128) {
        int n = u / 24, f4 = u % 24;
        int i = n / 7, j = n % 7;
        int gy = wy * 7 + i + SS_; if (gy >= HW_) gy -= HW_;
        int gx = wx * 7 + j + SS_; if (gx >= HW_) gx -= HW_;
        float4 v = *(const float4*)&x[(((size_t)b * HW_ + gy) * HW_ + gx) * C_ + f4 * 4];
        xsT[g][f4 * 4 + 0][n] = v.x; xsT[g][f4 * 4 + 1][n] = v.y;
        xsT[g][f4 * 4 + 2][n] = v.z; xsT[g][f4 * 4 + 3][n] = v.w;
    }
    if (tid < 2 * C_) xsT[tid / C_][tid % C_][49] = 0.0f;  // pad row for pairing

    const int tx = t % 24;   // column group (4 cols) within 96
    const int ty = t / 24;   // 0..4 active (10 rows each), ty==5 idles

    for (int which = 0; which < 3; which++) {
        ull acc[5][4] = {};    // 5 row-pairs x 4 cols
        #pragma unroll 1
        for (int sl = 0; sl < 8; sl++) {      // 8 slices of 12 K-rows
            __syncthreads();
            for (int u = tid; u < 12 * 24; u += 256) {
                int r = u / 24, f4 = u % 24;
                float4 v = *(const float4*)&qkv_w[(sl * 12 + r) * (3 * C_) + which * C_ + f4 * 4];
                ulonglong2 d0, d1;
                d0.x = splat2(v.x); d0.y = splat2(v.y);
                d1.x = splat2(v.z); d1.y = splat2(v.w);
                *(ulonglong2*)&wtd[r][f4 * 4]     = d0;
                *(ulonglong2*)&wtd[r][f4 * 4 + 2] = d1;
            }
            __syncthreads();
            if (ty < 5) {
                #pragma unroll 4
                for (int kk = 0; kk < 12; kk++) {
                    ulonglong2 wa = *(const ulonglong2*)&wtd[kk][tx * 4];
                    ulonglong2 wb = *(const ulonglong2*)&wtd[kk][tx * 4 + 2];
                    const float* xr = &xsT[g][sl * 12 + kk][ty * 10];
                    #pragma unroll
                    for (int p = 0; p < 5; p++) {
                        ull xp = *(const ull*)(xr + 2 * p);
                        ffma2(acc[p][0], xp, wa.x);
                        ffma2(acc[p][1], xp, wa.y);
                        ffma2(acc[p][2], xp, wb.x);
                        ffma2(acc[p][3], xp, wb.y);
                    }
                }
            }
        }
        if (ty < 5) {
            int c = tx * 4;
            int head = c >> 5, d = c & 31;
            float4 bias = *(const float4*)&qkv_b[which * C_ + c];
            float scale = (which == 0) ? 0.17677669529663687f : 1.0f; // hd^-0.5 (q only)
            size_t obase = ((size_t)(bw * 3 + head) * 3 + which) * (size_t)(N_ * HD_);
            #pragma unroll
            for (int p = 0; p < 5; p++) {
                float2 a0 = unpack2(acc[p][0]), a1 = unpack2(acc[p][1]);
                float2 a2 = unpack2(acc[p][2]), a3 = unpack2(acc[p][3]);
                int n = ty * 10 + 2 * p;
                float4 o;
                o.x = (a0.x + bias.x) * scale; o.y = (a1.x + bias.y) * scale;
                o.z = (a2.x + bias.z) * scale; o.w = (a3.x + bias.w) * scale;
                *(float4*)&g_qkv[obase + n * HD_ + d] = o;
                if (n + 1 < N_) {
                    o.x = (a0.y + bias.x) * scale; o.y = (a1.y + bias.y) * scale;
                    o.z = (a2.y + bias.z) * scale; o.w = (a3.y + bias.w) * scale;
                    *(float4*)&g_qkv[obase + (n + 1) * HD_ + d] = o;
                }
            }
        }
    }
}

// ---------------------------------------------------------------------------
// Kernel 2: windowed attention. grid = (BNW, 3), block = 128. (unchanged)
// ---------------------------------------------------------------------------
__global__ __launch_bounds__(128) void k_attn(const float* __restrict__ bias_table)
{
    __shared__ __align__(16) float qs[52][HD_];
    __shared__ __align__(16) float kT[HD_][56];
    __shared__ __align__(16) float vs[52][HD_];
    __shared__ __align__(16) float S[52][56];
    __shared__ int code[52];

    const int bw   = blockIdx.x;
    const int head = blockIdx.y;
    const int tid  = threadIdx.x;
    const size_t base = (size_t)(bw * 3 + head) * 3 * (size_t)(N_ * HD_);

    for (int u = tid; u < N_ * HD_; u += 128) {
        int n = u >> 5, d = u & 31;
        qs[n][d] = g_qkv[base + u];
        kT[d][n] = g_qkv[base + N_ * HD_ + u];
        vs[n][d] = g_qkv[base + 2 * N_ * HD_ + u];
    }
    {
        int w = bw & 255;
        int wy = w >> 4, wx = w & 15;
        for (int n = tid; n < N_; n += 128) {
            int i = n / 7, j = n % 7;
            int gy = wy * 7 + i + SS_; if (gy >= HW_) gy -= HW_;
            int gx = wx * 7 + j + SS_; if (gx >= HW_) gx -= HW_;
            code[n] = rcode(gy) * 3 + rcode(gx);
        }
    }
    __syncthreads();

    // S = q @ k^T  (49x49, K=32): tiles of 4 rows x 8 cols (m-pair packed)
    if (tid < 91) {
        int n0 = (tid / 7) * 4, m0 = (tid % 7) * 8;
        ull acc[4][4] = {};
        #pragma unroll 8
        for (int kk = 0; kk < HD_; kk++) {
            ulonglong2 ka = *(const ulonglong2*)&kT[kk][m0];
            ulonglong2 kb = *(const ulonglong2*)&kT[kk][m0 + 4];
            #pragma unroll
            for (int r = 0; r < 4; r++) {
                ull qsp = splat2(qs[n0 + r][kk]);
                ffma2(acc[r][0], ka.x, qsp);
                ffma2(acc[r][1], ka.y, qsp);
                ffma2(acc[r][2], kb.x, qsp);
                ffma2(acc[r][3], kb.y, qsp);
            }
        }
        #pragma unroll
        for (int r = 0; r < 4; r++) {
            ull* sr = (ull*)&S[n0 + r][m0];
            sr[0] = acc[r][0]; sr[1] = acc[r][1];
            sr[2] = acc[r][2]; sr[3] = acc[r][3];
        }
    }
    __syncthreads();

    // softmax rows, with relative-position bias + analytic shift mask
    const int wid = tid >> 5, lane = tid & 31;
    for (int r = wid; r < N_; r += 4) {
        int i1 = r / 7, j1 = r % 7, c1 = code[r];
        int m1 = lane, m2 = lane + 32;
        int i2 = m1 / 7, j2 = m1 % 7;
        float b1 = __ldg(&bias_table[((i1 - i2 + 6) * 13 + (j1 - j2 + 6)) * NH_ + head]);
        float v1 = S[r][m1] + b1 + (code[m1] == c1 ? 0.0f : -1e9f);
        float v2 = -1e30f;
        if (m2 < N_) {
            int i3 = m2 / 7, j3 = m2 % 7;
            float b2 = __ldg(&bias_table[((i1 - i3 + 6) * 13 + (j1 - j3 + 6)) * NH_ + head]);
            v2 = S[r][m2] + b2 + (code[m2] == c1 ? 0.0f : -1e9f);
        }
        float mx = fmaxf(v1, v2);
        #pragma unroll
        for (int o = 16; o > 0; o >>= 1) mx = fmaxf(mx, __shfl_xor_sync(0xffffffffu, mx, o));
        float e1 = __expf(v1 - mx);
        float e2 = (m2 < N_) ? __expf(v2 - mx) : 0.0f;
        float sum = e1 + e2;
        #pragma unroll
        for (int o = 16; o > 0; o >>= 1) sum += __shfl_xor_sync(0xffffffffu, sum, o);
        float inv = 1.0f / sum;
        S[r][m1] = e1 * inv;
        if (m2 < N_) S[r][m2] = e2 * inv;
    }
    __syncthreads();

    // O = P @ V  (49x32, K=49): tiles of 2 rows x 8 d (d-pair packed)
    if (tid < 100) {
        int n0 = (tid >> 2) * 2, d0 = (tid & 3) * 8;
        ull acc[2][4] = {};
        for (int m = 0; m < N_; m++) {
            ulonglong2 va = *(const ulonglong2*)&vs[m][d0];
            ulonglong2 vb = *(const ulonglong2*)&vs[m][d0 + 4];
            ull p0 = splat2(S[n0][m]);
            ull p1 = splat2(S[n0 + 1][m]);
            ffma2(acc[0][0], va.x, p0); ffma2(acc[0][1], va.y, p0);
            ffma2(acc[0][2], vb.x, p0); ffma2(acc[0][3], vb.y, p0);
            ffma2(acc[1][0], va.x, p1); ffma2(acc[1][1], va.y, p1);
            ffma2(acc[1][2], vb.x, p1); ffma2(acc[1][3], vb.y, p1);
        }
        #pragma unroll
        for (int r = 0; r < 2; r++) {
            int n = n0 + r;
            if (n < N_) {
                ull* o = (ull*)&g_y[((size_t)bw * N_ + n) * C_ + head * HD_ + d0];
                o[0] = acc[r][0]; o[1] = acc[r][1];
                o[2] = acc[r][2]; o[3] = acc[r][3];
            }
        }
    }
}

// ---------------------------------------------------------------------------
// Kernel 3: output projection + roll-scatter. grid = BNW/2, block = 256.
// ---------------------------------------------------------------------------
__global__ __launch_bounds__(256) void k_proj(
    const float* __restrict__ proj_w,
    const float* __restrict__ proj_b,
    float* __restrict__ out)
{
    __shared__ __align__(16) float ysT[2][C_][50];
    __shared__ __align__(16) ull   wtd[12][C_];

    const int tid = threadIdx.x;
    const int g   = tid >> 7;
    const int t   = tid & 127;
    const int bw  = blockIdx.x * 2 + g;

    for (int u = t; u < N_ * 24; u += 128) {
        int n = u / 24, f4 = u % 24;
        float4 v = *(const float4*)&g_y[(size_t)bw * (N_ * C_) + n * C_ + f4 * 4];
        ysT[g][f4 * 4 + 0][n] = v.x; ysT[g][f4 * 4 + 1][n] = v.y;
        ysT[g][f4 * 4 + 2][n] = v.z; ysT[g][f4 * 4 + 3][n] = v.w;
    }
    if (tid < 2 * C_) ysT[tid / C_][tid % C_][49] = 0.0f;

    const int tx = t % 24;
    const int ty = t / 24;

    ull acc[5][4] = {};
    #pragma unroll 1
    for (int sl = 0; sl < 8; sl++) {
        __syncthreads();
        for (int u = tid; u < 12 * 24; u += 256) {
            int r = u / 24, f4 = u % 24;
            float4 v = *(const float4*)&proj_w[(sl * 12 + r) * C_ + f4 * 4];
            ulonglong2 d0, d1;
            d0.x = splat2(v.x); d0.y = splat2(v.y);
            d1.x = splat2(v.z); d1.y = splat2(v.w);
            *(ulonglong2*)&wtd[r][f4 * 4]     = d0;
            *(ulonglong2*)&wtd[r][f4 * 4 + 2] = d1;
        }
        __syncthreads();
        if (ty < 5) {
            #pragma unroll 4
            for (int kk = 0; kk < 12; kk++) {
                ulonglong2 wa = *(const ulonglong2*)&wtd[kk][tx * 4];
                ulonglong2 wb = *(const ulonglong2*)&wtd[kk][tx * 4 + 2];
                const float* yr = &ysT[g][sl * 12 + kk][ty * 10];
                #pragma unroll
                for (int p = 0; p < 5; p++) {
                    ull yp = *(const ull*)(yr + 2 * p);
                    ffma2(acc[p][0], yp, wa.x);
                    ffma2(acc[p][1], yp, wa.y);
                    ffma2(acc[p][2], yp, wb.x);
                    ffma2(acc[p][3], yp, wb.y);
                }
            }
        }
    }

    if (ty < 5) {
        const int b  = bw >> 8;
        const int w  = bw & 255;
        const int wy = w >> 4, wx = w & 15;
        float4 bias = *(const float4*)&proj_b[tx * 4];
        #pragma unroll
        for (int p = 0; p < 5; p++) {
            float2 a0 = unpack2(acc[p][0]), a1 = unpack2(acc[p][1]);
            float2 a2 = unpack2(acc[p][2]), a3 = unpack2(acc[p][3]);
            float r0[2] = {a0.x, a0.y}, r1[2] = {a1.x, a1.y};
            float r2[2] = {a2.x, a2.y}, r3[2] = {a3.x, a3.y};
            #pragma unroll
            for (int h = 0; h < 2; h++) {
                int n = ty * 10 + 2 * p + h;
                if (n < N_) {
                    int i = n / 7, j = n % 7;
                    int gy = wy * 7 + i + SS_; if (gy >= HW_) gy -= HW_;
                    int gx = wx * 7 + j + SS_; if (gx >= HW_) gx -= HW_;
                    float4 o;
                    o.x = r0[h] + bias.x; o.y = r1[h] + bias.y;
                    o.z = r2[h] + bias.z; o.w = r3[h] + bias.w;
                    *(float4*)&out[(((size_t)b * HW_ + gy) * HW_ + gx) * C_ + tx * 4] = o;
                }
            }
        }
    }
}

// ---------------------------------------------------------------------------
extern "C" void kernel_launch(void* const* d_in, const int* in_sizes, int n_in,
                              void* d_out, int out_size)
{
    (void)in_sizes; (void)n_in; (void)out_size;
    const float* x          = (const float*)d_in[0];
    const float* qkv_w      = (const float*)d_in[1];
    const float* qkv_b      = (const float*)d_in[2];
    const float* proj_w     = (const float*)d_in[3];
    const float* proj_b     = (const float*)d_in[4];
    const float* bias_table = (const float*)d_in[5];
    float* out = (float*)d_out;

    k_qkv <<<BNW / 2, 256>>>(x, qkv_w, qkv_b);
    k_attn<<<dim3(BNW, NH_), 128>>>(bias_table);
    k_proj<<<BNW / 2, 256>>>(proj_w, proj_b, out);
}

// round 10
// speedup vs baseline: 1.3076x; 1.3076x over previous
#include <cuda_runtime.h>
#include <cuda_bf16.h>
#include <cstdint>

// Swin shifted-window MSA: B=32, H=W=112, C=96, ws=7, ss=3, nh=3, hd=32
// Round 9: tcgen05 is unavailable (harness targets sm_103, not sm_103a).
// Use classic mma.sync (HMMA) bf16 with hi/lo 3-term split for QKV/proj GEMMs,
// computed in natural token layout (projections commute with roll/window perm).
// Attention stays fp32 FFMA2, token-indexed.

#define WS_ 7
#define SS_ 3
#define NH_ 3
#define HD_ 32
#define C_  96
#define N_  49
#define HW_ 112
#define BNW 8192
#define NTOK 401408          // 32*112*112 = 3136 * 128
#define MTILES 3136

typedef unsigned long long ull;

// scratch (static device globals; no allocation anywhere)
__device__ float g_qkv[(size_t)NTOK * 288];  // [token][which*96 + c]
__device__ float g_y[(size_t)NTOK * 96];     // [token][c]

__device__ __forceinline__ int rcode(int h) {
    return h < (HW_ - WS_) ? 0 : (h < (HW_ - SS_) ? 1 : 2);
}
__device__ __forceinline__ ull splat2(float v) {
    ull r; asm("mov.b64 %0, {%1, %1};" : "=l"(r) : "f"(v)); return r;
}
__device__ __forceinline__ void ffma2(ull& d, ull a, ull b) {
    asm("fma.rn.f32x2 %0, %1, %2, %0;" : "+l"(d) : "l"(a), "l"(b));
}

// HMMA m16n8k16 row.col f32 += bf16*bf16
__device__ __forceinline__ void mma_bf16(float* d, const uint32_t* a, const uint32_t* b) {
    asm volatile(
        "mma.sync.aligned.m16n8k16.row.col.f32.bf16.bf16.f32 "
        "{%0,%1,%2,%3}, {%4,%5,%6,%7}, {%8,%9}, {%0,%1,%2,%3};"
        : "+f"(d[0]), "+f"(d[1]), "+f"(d[2]), "+f"(d[3])
        : "r"(a[0]), "r"(a[1]), "r"(a[2]), "r"(a[3]), "r"(b[0]), "r"(b[1]));
}

// smem tiles: bf16, row stride 100 ushorts (200B -> conflict-free pattern)
#define ASTR 100
#define AH_OFF 0
#define AL_OFF 25600
#define BH_OFF 51200
#define BL_OFF 70400
#define SMEM_DYN 89600

// ---------------------------------------------------------------------------
// HMMA GEMM: out[m][which*96+n] = (sum_k in[m][k]*wmat[k][which*96+n] + bias)*sc
// grid = MTILES, block = 256 (8 warps; warp w owns rows 16w..16w+15).
// ---------------------------------------------------------------------------
__global__ __launch_bounds__(256) void k_gemm(
    const float* __restrict__ in,    // [NTOK][96]
    const float* __restrict__ wmat,  // [96][wstride]
    const float* __restrict__ bias,  // [wstride]
    float* __restrict__ outp,        // [NTOK][wstride]
    int wstride, int nwhich, float scale0)
{
    extern __shared__ char smem[];
    unsigned short* AH = (unsigned short*)(smem + AH_OFF);
    unsigned short* AL = (unsigned short*)(smem + AL_OFF);
    unsigned short* BH = (unsigned short*)(smem + BH_OFF);
    unsigned short* BL = (unsigned short*)(smem + BL_OFF);

    const int tid  = threadIdx.x;
    const int wrp  = tid >> 5;
    const int lane = tid & 31;
    const int grp  = lane >> 2;      // 0..7
    const int tig  = lane & 3;       // 0..3
    const size_t m0 = (size_t)blockIdx.x * 128;

    // ---- A fill: 128 x 96 f32 -> bf16 hi/lo (rows of the token matrix) ----
    for (int u = tid; u < 128 * 24; u += 256) {
        int r = u / 24, f4 = u % 24;
        float4 v = *(const float4*)&in[(m0 + r) * 96 + f4 * 4];
        float vv[4] = {v.x, v.y, v.z, v.w};
        ull hh = 0, ll = 0;
        #pragma unroll
        for (int e = 0; e < 4; e++) {
            __nv_bfloat16 h = __float2bfloat16_rn(vv[e]);
            __nv_bfloat16 l = __float2bfloat16_rn(vv[e] - __bfloat162float(h));
            hh |= (ull)__bfloat16_as_ushort(h) << (16 * e);
            ll |= (ull)__bfloat16_as_ushort(l) << (16 * e);
        }
        *(ull*)&AH[r * ASTR + f4 * 4] = hh;
        *(ull*)&AL[r * ASTR + f4 * 4] = ll;
    }

    for (int which = 0; which < nwhich; which++) {
        __syncthreads();   // A ready (iter 0) / previous compute done (iter >0)
        // ---- B fill (transposed): Bt[n][k] = wmat[k][which*96+n], hi/lo ----
        for (int u = tid; u < 96 * 24; u += 256) {
            int k = u / 24, f4 = u % 24;
            float4 v = __ldg((const float4*)&wmat[(size_t)k * wstride + which * 96 + f4 * 4]);
            float vv[4] = {v.x, v.y, v.z, v.w};
            #pragma unroll
            for (int e = 0; e < 4; e++) {
                int n = f4 * 4 + e;
                __nv_bfloat16 h = __float2bfloat16_rn(vv[e]);
                __nv_bfloat16 l = __float2bfloat16_rn(vv[e] - __bfloat162float(h));
                BH[n * ASTR + k] = __bfloat16_as_ushort(h);
                BL[n * ASTR + k] = __bfloat16_as_ushort(l);
            }
        }
        __syncthreads();

        // ---- compute: warp computes 16 x 96, K=96, 3 terms ----
        float acc[12][4] = {};
        const int ar0 = (wrp * 16 + grp) * ASTR;       // A row base (upper 8)
        const int ar1 = (wrp * 16 + grp + 8) * ASTR;   // lower 8
        #pragma unroll
        for (int ks = 0; ks < 6; ks++) {
            const int kc = ks * 16 + tig * 2;
            uint32_t ah[4], al[4];
            ah[0] = *(const uint32_t*)&AH[ar0 + kc];
            ah[1] = *(const uint32_t*)&AH[ar1 + kc];
            ah[2] = *(const uint32_t*)&AH[ar0 + kc + 8];
            ah[3] = *(const uint32_t*)&AH[ar1 + kc + 8];
            al[0] = *(const uint32_t*)&AL[ar0 + kc];
            al[1] = *(const uint32_t*)&AL[ar1 + kc];
            al[2] = *(const uint32_t*)&AL[ar0 + kc + 8];
            al[3] = *(const uint32_t*)&AL[ar1 + kc + 8];
            #pragma unroll
            for (int nt = 0; nt < 12; nt++) {
                const int br = (nt * 8 + grp) * ASTR;
                uint32_t bh[2], bl[2];
                bh[0] = *(const uint32_t*)&BH[br + kc];
                bh[1] = *(const uint32_t*)&BH[br + kc + 8];
                bl[0] = *(const uint32_t*)&BL[br + kc];
                bl[1] = *(const uint32_t*)&BL[br + kc + 8];
                mma_bf16(acc[nt], ah, bh);   // hi*hi
                mma_bf16(acc[nt], ah, bl);   // hi*lo
                mma_bf16(acc[nt], al, bh);   // lo*hi
            }
        }

        // ---- epilogue: bias + scale, direct stores ----
        const float sc = (which == 0) ? scale0 : 1.0f;
        const size_t row0 = m0 + wrp * 16 + grp;
        #pragma unroll
        for (int nt = 0; nt < 12; nt++) {
            int col = which * 96 + nt * 8 + tig * 2;
            float2 bv = __ldg((const float2*)&bias[col]);
            float2 o0, o1;
            o0.x = (acc[nt][0] + bv.x) * sc; o0.y = (acc[nt][1] + bv.y) * sc;
            o1.x = (acc[nt][2] + bv.x) * sc; o1.y = (acc[nt][3] + bv.y) * sc;
            *(float2*)&outp[row0 * wstride + col] = o0;
            *(float2*)&outp[(row0 + 8) * wstride + col] = o1;
        }
    }
}

// ---------------------------------------------------------------------------
// Windowed attention (fp32 FFMA2), token-indexed. grid = (BNW, 3), block = 128.
// ---------------------------------------------------------------------------
__global__ __launch_bounds__(128) void k_attn(const float* __restrict__ bias_table)
{
    __shared__ __align__(16) float qs[52][HD_];
    __shared__ __align__(16) float kT[HD_][56];
    __shared__ __align__(16) float vs[52][HD_];
    __shared__ __align__(16) float S[52][56];
    __shared__ int code[52];
    __shared__ int tokv[52];

    const int bw   = blockIdx.x;
    const int head = blockIdx.y;
    const int tid  = threadIdx.x;

    {
        int b = bw >> 8, w = bw & 255;
        int wy = w >> 4, wx = w & 15;
        for (int n = tid; n < N_; n += 128) {
            int i = n / 7, j = n % 7;
            int gy = wy * 7 + i + SS_; if (gy >= HW_) gy -= HW_;
            int gx = wx * 7 + j + SS_; if (gx >= HW_) gx -= HW_;
            tokv[n] = (b * HW_ + gy) * HW_ + gx;
            code[n] = rcode(gy) * 3 + rcode(gx);
        }
    }
    __syncthreads();

    for (int u = tid; u < N_ * HD_; u += 128) {
        int n = u >> 5, d = u & 31;
        const float* row = g_qkv + (size_t)tokv[n] * 288 + head * HD_ + d;
        qs[n][d] = row[0];
        kT[d][n] = row[96];
        vs[n][d] = row[192];
    }
    __syncthreads();

    // S = q @ k^T  (49x49, K=32): tiles of 4 rows x 8 cols (m-pair packed)
    if (tid < 91) {
        int n0 = (tid / 7) * 4, m0 = (tid % 7) * 8;
        ull acc[4][4] = {};
        #pragma unroll 8
        for (int kk = 0; kk < HD_; kk++) {
            ulonglong2 ka = *(const ulonglong2*)&kT[kk][m0];
            ulonglong2 kb = *(const ulonglong2*)&kT[kk][m0 + 4];
            #pragma unroll
            for (int r = 0; r < 4; r++) {
                ull qsp = splat2(qs[n0 + r][kk]);
                ffma2(acc[r][0], ka.x, qsp);
                ffma2(acc[r][1], ka.y, qsp);
                ffma2(acc[r][2], kb.x, qsp);
                ffma2(acc[r][3], kb.y, qsp);
            }
        }
        #pragma unroll
        for (int r = 0; r < 4; r++) {
            ull* sr = (ull*)&S[n0 + r][m0];
            sr[0] = acc[r][0]; sr[1] = acc[r][1];
            sr[2] = acc[r][2]; sr[3] = acc[r][3];
        }
    }
    __syncthreads();

    // softmax rows, with relative-position bias + analytic shift mask
    const int wid = tid >> 5, lane = tid & 31;
    for (int r = wid; r < N_; r += 4) {
        int i1 = r / 7, j1 = r % 7, c1 = code[r];
        int m1 = lane, m2 = lane + 32;
        int i2 = m1 / 7, j2 = m1 % 7;
        float b1 = __ldg(&bias_table[((i1 - i2 + 6) * 13 + (j1 - j2 + 6)) * NH_ + head]);
        float v1 = S[r][m1] + b1 + (code[m1] == c1 ? 0.0f : -1e9f);
        float v2 = -1e30f;
        if (m2 < N_) {
            int i3 = m2 / 7, j3 = m2 % 7;
            float b2 = __ldg(&bias_table[((i1 - i3 + 6) * 13 + (j1 - j3 + 6)) * NH_ + head]);
            v2 = S[r][m2] + b2 + (code[m2] == c1 ? 0.0f : -1e9f);
        }
        float mx = fmaxf(v1, v2);
        #pragma unroll
        for (int o = 16; o > 0; o >>= 1) mx = fmaxf(mx, __shfl_xor_sync(0xffffffffu, mx, o));
        float e1 = __expf(v1 - mx);
        float e2 = (m2 < N_) ? __expf(v2 - mx) : 0.0f;
        float sum = e1 + e2;
        #pragma unroll
        for (int o = 16; o > 0; o >>= 1) sum += __shfl_xor_sync(0xffffffffu, sum, o);
        float inv = 1.0f / sum;
        S[r][m1] = e1 * inv;
        if (m2 < N_) S[r][m2] = e2 * inv;
    }
    __syncthreads();

    // O = P @ V  (49x32, K=49): tiles of 2 rows x 8 d (d-pair packed)
    if (tid < 100) {
        int n0 = (tid >> 2) * 2, d0 = (tid & 3) * 8;
        ull acc[2][4] = {};
        for (int m = 0; m < N_; m++) {
            ulonglong2 va = *(const ulonglong2*)&vs[m][d0];
            ulonglong2 vb = *(const ulonglong2*)&vs[m][d0 + 4];
            ull p0 = splat2(S[n0][m]);
            ull p1 = splat2(S[n0 + 1][m]);
            ffma2(acc[0][0], va.x, p0); ffma2(acc[0][1], va.y, p0);
            ffma2(acc[0][2], vb.x, p0); ffma2(acc[0][3], vb.y, p0);
            ffma2(acc[1][0], va.x, p1); ffma2(acc[1][1], va.y, p1);
            ffma2(acc[1][2], vb.x, p1); ffma2(acc[1][3], vb.y, p1);
        }
        #pragma unroll
        for (int r = 0; r < 2; r++) {
            int n = n0 + r;
            if (n < N_) {
                ull* o = (ull*)&g_y[(size_t)tokv[n] * 96 + head * HD_ + d0];
                o[0] = acc[r][0]; o[1] = acc[r][1];
                o[2] = acc[r][2]; o[3] = acc[r][3];
            }
        }
    }
}

// ---------------------------------------------------------------------------
extern "C" void kernel_launch(void* const* d_in, const int* in_sizes, int n_in,
                              void* d_out, int out_size)
{
    (void)in_sizes; (void)n_in; (void)out_size;
    const float* x          = (const float*)d_in[0];
    const float* qkv_w      = (const float*)d_in[1];
    const float* qkv_b      = (const float*)d_in[2];
    const float* proj_w     = (const float*)d_in[3];
    const float* proj_b     = (const float*)d_in[4];
    const float* bias_table = (const float*)d_in[5];
    float* out = (float*)d_out;

    void *pqkv = nullptr, *py = nullptr;
    cudaGetSymbolAddress(&pqkv, g_qkv);
    cudaGetSymbolAddress(&py, g_y);
    static bool attr_done = false;
    if (!attr_done) {
        cudaFuncSetAttribute(k_gemm, cudaFuncAttributeMaxDynamicSharedMemorySize, SMEM_DYN);
        attr_done = true;
    }

    // QKV: [NTOK,96] @ [96,288] (+bias, q-scale), token-natural
    k_gemm<<<MTILES, 256, SMEM_DYN>>>(x, qkv_w, qkv_b, (float*)pqkv,
                                      288, 3, 0.17677669529663687f);
    // attention (token-indexed gather/scatter)
    k_attn<<<dim3(BNW, NH_), 128>>>(bias_table);
    // proj: [NTOK,96] @ [96,96] (+bias) -> out (token-natural, no roll needed)
    k_gemm<<<MTILES, 256, SMEM_DYN>>>((const float*)py, proj_w, proj_b, out,
                                      96, 1, 1.0f);
}

// round 11
// speedup vs baseline: 1.3215x; 1.0107x over previous
#include <cuda_runtime.h>
#include <cuda_bf16.h>
#include <cstdint>

// Swin shifted-window MSA: B=32, H=W=112, C=96, ws=7, ss=3, nh=3, hd=32
// Round 10: k_gemm fragment loads via ldmatrix.m8n8.x4 (4x fewer LSU ops;
// R9 was L1/LDS-bound at 82.7% with tensor pipe starved at 25.9%).
// Token-natural HMMA bf16 hi/lo split GEMMs; attention unchanged (fp32 FFMA2).

#define WS_ 7
#define SS_ 3
#define NH_ 3
#define HD_ 32
#define C_  96
#define N_  49
#define HW_ 112
#define BNW 8192
#define NTOK 401408          // 32*112*112 = 3136 * 128
#define MTILES 3136

typedef unsigned long long ull;

// scratch (static device globals; no allocation anywhere)
__device__ float g_qkv[(size_t)NTOK * 288];  // [token][which*96 + c]
__device__ float g_y[(size_t)NTOK * 96];     // [token][c]

__device__ __forceinline__ int rcode(int h) {
    return h < (HW_ - WS_) ? 0 : (h < (HW_ - SS_) ? 1 : 2);
}
__device__ __forceinline__ ull splat2(float v) {
    ull r; asm("mov.b64 %0, {%1, %1};" : "=l"(r) : "f"(v)); return r;
}
__device__ __forceinline__ void ffma2(ull& d, ull a, ull b) {
    asm("fma.rn.f32x2 %0, %1, %2, %0;" : "+l"(d) : "l"(a), "l"(b));
}
__device__ __forceinline__ uint32_t smem_u32(const void* p) {
    uint32_t a;
    asm("{ .reg .u64 t; cvta.to.shared.u64 t, %1; cvt.u32.u64 %0, t; }" : "=r"(a) : "l"(p));
    return a;
}

// HMMA m16n8k16 row.col f32 += bf16*bf16
__device__ __forceinline__ void mma_bf16(float* d, const uint32_t* a, const uint32_t* b) {
    asm volatile(
        "mma.sync.aligned.m16n8k16.row.col.f32.bf16.bf16.f32 "
        "{%0,%1,%2,%3}, {%4,%5,%6,%7}, {%8,%9}, {%0,%1,%2,%3};"
        : "+f"(d[0]), "+f"(d[1]), "+f"(d[2]), "+f"(d[3])
        : "r"(a[0]), "r"(a[1]), "r"(a[2]), "r"(a[3]), "r"(b[0]), "r"(b[1]));
}
#define LDSM4(r, addr) \
    asm volatile("ldmatrix.sync.aligned.m8n8.x4.shared.b16 {%0,%1,%2,%3}, [%4];" \
        : "=r"((r)[0]), "=r"((r)[1]), "=r"((r)[2]), "=r"((r)[3]) : "r"(addr))

// smem tiles: bf16, row stride 104 ushorts (208B) -> conflict-free ldmatrix
#define ASTR 104
#define ROWB 208
#define AH_OFF 0
#define AL_OFF 26624
#define BH_OFF 53248
#define BL_OFF 73216
#define SMEM_DYN 93184

// ---------------------------------------------------------------------------
// HMMA GEMM: out[m][which*96+n] = (sum_k in[m][k]*wmat[k][which*96+n] + bias)*sc
// grid = MTILES, block = 256 (8 warps; warp w owns rows 16w..16w+15).
// ---------------------------------------------------------------------------
__global__ __launch_bounds__(256) void k_gemm(
    const float* __restrict__ in,    // [NTOK][96]
    const float* __restrict__ wmat,  // [96][wstride]
    const float* __restrict__ bias,  // [wstride]
    float* __restrict__ outp,        // [NTOK][wstride]
    int wstride, int nwhich, float scale0)
{
    extern __shared__ char smem[];
    unsigned short* AH = (unsigned short*)(smem + AH_OFF);
    unsigned short* AL = (unsigned short*)(smem + AL_OFF);
    unsigned short* BH = (unsigned short*)(smem + BH_OFF);
    unsigned short* BL = (unsigned short*)(smem + BL_OFF);

    const int tid  = threadIdx.x;
    const int wrp  = tid >> 5;
    const int lane = tid & 31;
    const int grp  = lane >> 2;      // 0..7
    const int tig  = lane & 3;       // 0..3
    const size_t m0 = (size_t)blockIdx.x * 128;

    // per-lane ldmatrix base addresses (byte offsets into smem)
    const uint32_t sbase = smem_u32(smem);
    // A: row = warpRow + (lane&15), col halves by bit4
    const uint32_t aoff =
        (uint32_t)(wrp * 16 + (lane & 15)) * ROWB + ((lane & 16) ? 16u : 0u);
    const uint32_t aAddrH = sbase + AH_OFF + aoff;
    const uint32_t aAddrL = sbase + AL_OFF + aoff;
    // B: row n = (lane&7) + bit4*8 (pair-local), col halves by bit3
    const uint32_t boff =
        (uint32_t)((lane & 7) + ((lane & 16) ? 8 : 0)) * ROWB + ((lane & 8) ? 16u : 0u);
    const uint32_t bAddrH = sbase + BH_OFF + boff;
    const uint32_t bAddrL = sbase + BL_OFF + boff;

    // ---- A fill: 128 x 96 f32 -> bf16 hi/lo ----
    for (int u = tid; u < 128 * 24; u += 256) {
        int r = u / 24, f4 = u % 24;
        float4 v = *(const float4*)&in[(m0 + r) * 96 + f4 * 4];
        float vv[4] = {v.x, v.y, v.z, v.w};
        ull hh = 0, ll = 0;
        #pragma unroll
        for (int e = 0; e < 4; e++) {
            __nv_bfloat16 h = __float2bfloat16_rn(vv[e]);
            __nv_bfloat16 l = __float2bfloat16_rn(vv[e] - __bfloat162float(h));
            hh |= (ull)__bfloat16_as_ushort(h) << (16 * e);
            ll |= (ull)__bfloat16_as_ushort(l) << (16 * e);
        }
        *(ull*)&AH[r * ASTR + f4 * 4] = hh;
        *(ull*)&AL[r * ASTR + f4 * 4] = ll;
    }

    for (int which = 0; which < nwhich; which++) {
        __syncthreads();   // A ready (iter 0) / previous compute done (iter >0)
        // ---- B fill (transposed): Bt[n][k] = wmat[k][which*96+n], hi/lo ----
        for (int u = tid; u < 96 * 24; u += 256) {
            int k = u / 24, f4 = u % 24;
            float4 v = __ldg((const float4*)&wmat[(size_t)k * wstride + which * 96 + f4 * 4]);
            float vv[4] = {v.x, v.y, v.z, v.w};
            #pragma unroll
            for (int e = 0; e < 4; e++) {
                int n = f4 * 4 + e;
                __nv_bfloat16 h = __float2bfloat16_rn(vv[e]);
                __nv_bfloat16 l = __float2bfloat16_rn(vv[e] - __bfloat162float(h));
                BH[n * ASTR + k] = __bfloat16_as_ushort(h);
                BL[n * ASTR + k] = __bfloat16_as_ushort(l);
            }
        }
        __syncthreads();

        // ---- compute: warp computes 16 x 96, K=96, 3-term bf16 split ----
        float acc[12][4] = {};
        #pragma unroll
        for (int ks = 0; ks < 6; ks++) {
            uint32_t ah[4], al[4];
            LDSM4(ah, aAddrH + ks * 32);
            LDSM4(al, aAddrL + ks * 32);
            #pragma unroll
            for (int p = 0; p < 6; p++) {
                uint32_t bh[4], bl[4];
                const uint32_t bo = (uint32_t)(p * 16 * ROWB + ks * 32);
                LDSM4(bh, bAddrH + bo);
                LDSM4(bl, bAddrL + bo);
                mma_bf16(acc[2 * p],     ah, bh);       // hi*hi (even nt)
                mma_bf16(acc[2 * p],     ah, bl);       // hi*lo
                mma_bf16(acc[2 * p],     al, bh);       // lo*hi
                mma_bf16(acc[2 * p + 1], ah, bh + 2);   // odd nt
                mma_bf16(acc[2 * p + 1], ah, bl + 2);
                mma_bf16(acc[2 * p + 1], al, bh + 2);
            }
        }

        // ---- epilogue: bias + scale, direct stores ----
        const float sc = (which == 0) ? scale0 : 1.0f;
        const size_t row0 = m0 + wrp * 16 + grp;
        #pragma unroll
        for (int nt = 0; nt < 12; nt++) {
            int col = which * 96 + nt * 8 + tig * 2;
            float2 bv = __ldg((const float2*)&bias[col]);
            float2 o0, o1;
            o0.x = (acc[nt][0] + bv.x) * sc; o0.y = (acc[nt][1] + bv.y) * sc;
            o1.x = (acc[nt][2] + bv.x) * sc; o1.y = (acc[nt][3] + bv.y) * sc;
            *(float2*)&outp[row0 * wstride + col] = o0;
            *(float2*)&outp[(row0 + 8) * wstride + col] = o1;
        }
    }
}

// ---------------------------------------------------------------------------
// Windowed attention (fp32 FFMA2), token-indexed. grid = (BNW, 3), block = 128.
// ---------------------------------------------------------------------------
__global__ __launch_bounds__(128) void k_attn(const float* __restrict__ bias_table)
{
    __shared__ __align__(16) float qs[52][HD_];
    __shared__ __align__(16) float kT[HD_][56];
    __shared__ __align__(16) float vs[52][HD_];
    __shared__ __align__(16) float S[52][56];
    __shared__ int code[52];
    __shared__ int tokv[52];

    const int bw   = blockIdx.x;
    const int head = blockIdx.y;
    const int tid  = threadIdx.x;

    {
        int b = bw >> 8, w = bw & 255;
        int wy = w >> 4, wx = w & 15;
        for (int n = tid; n < N_; n += 128) {
            int i = n / 7, j = n % 7;
            int gy = wy * 7 + i + SS_; if (gy >= HW_) gy -= HW_;
            int gx = wx * 7 + j + SS_; if (gx >= HW_) gx -= HW_;
            tokv[n] = (b * HW_ + gy) * HW_ + gx;
            code[n] = rcode(gy) * 3 + rcode(gx);
        }
    }
    __syncthreads();

    for (int u = tid; u < N_ * HD_; u += 128) {
        int n = u >> 5, d = u & 31;
        const float* row = g_qkv + (size_t)tokv[n] * 288 + head * HD_ + d;
        qs[n][d] = row[0];
        kT[d][n] = row[96];
        vs[n][d] = row[192];
    }
    __syncthreads();

    // S = q @ k^T  (49x49, K=32): tiles of 4 rows x 8 cols (m-pair packed)
    if (tid < 91) {
        int n0 = (tid / 7) * 4, m0 = (tid % 7) * 8;
        ull acc[4][4] = {};
        #pragma unroll 8
        for (int kk = 0; kk < HD_; kk++) {
            ulonglong2 ka = *(const ulonglong2*)&kT[kk][m0];
            ulonglong2 kb = *(const ulonglong2*)&kT[kk][m0 + 4];
            #pragma unroll
            for (int r = 0; r < 4; r++) {
                ull qsp = splat2(qs[n0 + r][kk]);
                ffma2(acc[r][0], ka.x, qsp);
                ffma2(acc[r][1], ka.y, qsp);
                ffma2(acc[r][2], kb.x, qsp);
                ffma2(acc[r][3], kb.y, qsp);
            }
        }
        #pragma unroll
        for (int r = 0; r < 4; r++) {
            ull* sr = (ull*)&S[n0 + r][m0];
            sr[0] = acc[r][0]; sr[1] = acc[r][1];
            sr[2] = acc[r][2]; sr[3] = acc[r][3];
        }
    }
    __syncthreads();

    // softmax rows, with relative-position bias + analytic shift mask
    const int wid = tid >> 5, lane = tid & 31;
    for (int r = wid; r < N_; r += 4) {
        int i1 = r / 7, j1 = r % 7, c1 = code[r];
        int m1 = lane, m2 = lane + 32;
        int i2 = m1 / 7, j2 = m1 % 7;
        float b1 = __ldg(&bias_table[((i1 - i2 + 6) * 13 + (j1 - j2 + 6)) * NH_ + head]);
        float v1 = S[r][m1] + b1 + (code[m1] == c1 ? 0.0f : -1e9f);
        float v2 = -1e30f;
        if (m2 < N_) {
            int i3 = m2 / 7, j3 = m2 % 7;
            float b2 = __ldg(&bias_table[((i1 - i3 + 6) * 13 + (j1 - j3 + 6)) * NH_ + head]);
            v2 = S[r][m2] + b2 + (code[m2] == c1 ? 0.0f : -1e9f);
        }
        float mx = fmaxf(v1, v2);
        #pragma unroll
        for (int o = 16; o > 0; o >>= 1) mx = fmaxf(mx, __shfl_xor_sync(0xffffffffu, mx, o));
        float e1 = __expf(v1 - mx);
        float e2 = (m2 < N_) ? __expf(v2 - mx) : 0.0f;
        float sum = e1 + e2;
        #pragma unroll
        for (int o = 16; o > 0; o >>= 1) sum += __shfl_xor_sync(0xffffffffu, sum, o);
        float inv = 1.0f / sum;
        S[r][m1] = e1 * inv;
        if (m2 < N_) S[r][m2] = e2 * inv;
    }
    __syncthreads();

    // O = P @ V  (49x32, K=49): tiles of 2 rows x 8 d (d-pair packed)
    if (tid < 100) {
        int n0 = (tid >> 2) * 2, d0 = (tid & 3) * 8;
        ull acc[2][4] = {};
        for (int m = 0; m < N_; m++) {
            ulonglong2 va = *(const ulonglong2*)&vs[m][d0];
            ulonglong2 vb = *(const ulonglong2*)&vs[m][d0 + 4];
            ull p0 = splat2(S[n0][m]);
            ull p1 = splat2(S[n0 + 1][m]);
            ffma2(acc[0][0], va.x, p0); ffma2(acc[0][1], va.y, p0);
            ffma2(acc[0][2], vb.x, p0); ffma2(acc[0][3], vb.y, p0);
            ffma2(acc[1][0], va.x, p1); ffma2(acc[1][1], va.y, p1);
            ffma2(acc[1][2], vb.x, p1); ffma2(acc[1][3], vb.y, p1);
        }
        #pragma unroll
        for (int r = 0; r < 2; r++) {
            int n = n0 + r;
            if (n < N_) {
                ull* o = (ull*)&g_y[(size_t)tokv[n] * 96 + head * HD_ + d0];
                o[0] = acc[r][0]; o[1] = acc[r][1];
                o[2] = acc[r][2]; o[3] = acc[r][3];
            }
        }
    }
}

// ---------------------------------------------------------------------------
extern "C" void kernel_launch(void* const* d_in, const int* in_sizes, int n_in,
                              void* d_out, int out_size)
{
    (void)in_sizes; (void)n_in; (void)out_size;
    const float* x          = (const float*)d_in[0];
    const float* qkv_w      = (const float*)d_in[1];
    const float* qkv_b      = (const float*)d_in[2];
    const float* proj_w     = (const float*)d_in[3];
    const float* proj_b     = (const float*)d_in[4];
    const float* bias_table = (const float*)d_in[5];
    float* out = (float*)d_out;

    void *pqkv = nullptr, *py = nullptr;
    cudaGetSymbolAddress(&pqkv, g_qkv);
    cudaGetSymbolAddress(&py, g_y);
    static bool attr_done = false;
    if (!attr_done) {
        cudaFuncSetAttribute(k_gemm, cudaFuncAttributeMaxDynamicSharedMemorySize, SMEM_DYN);
        attr_done = true;
    }

    // QKV: [NTOK,96] @ [96,288] (+bias, q-scale), token-natural
    k_gemm<<<MTILES, 256, SMEM_DYN>>>(x, qkv_w, qkv_b, (float*)pqkv,
                                      288, 3, 0.17677669529663687f);
    // attention (token-indexed gather/scatter)
    k_attn<<<dim3(BNW, NH_), 128>>>(bias_table);
    // proj: [NTOK,96] @ [96,96] (+bias) -> out (token-natural, no roll needed)
    k_gemm<<<MTILES, 256, SMEM_DYN>>>((const float*)py, proj_w, proj_b, out,
                                      96, 1, 1.0f);
}

// round 12
// speedup vs baseline: 1.4634x; 1.1073x over previous
#include <cuda_runtime.h>
#include <cuda_bf16.h>
#include <cstdint>

// Swin shifted-window MSA: B=32, H=W=112, C=96, ws=7, ss=3, nh=3, hd=32
// Round 11: HMMA-ize k_attn (S=qk^T and O=PV as m16n8k16 bf16 hi/lo 3-term
// split mmas). k_gemm unchanged from R10 (token-natural HMMA split GEMMs).

#define WS_ 7
#define SS_ 3
#define NH_ 3
#define HD_ 32
#define C_  96
#define N_  49
#define HW_ 112
#define BNW 8192
#define NTOK 401408          // 32*112*112 = 3136 * 128
#define MTILES 3136

typedef unsigned long long ull;

// scratch (static device globals; no allocation anywhere)
__device__ float g_qkv[(size_t)NTOK * 288];  // [token][which*96 + c]
__device__ float g_y[(size_t)NTOK * 96];     // [token][c]

__device__ __forceinline__ int rcode(int h) {
    return h < (HW_ - WS_) ? 0 : (h < (HW_ - SS_) ? 1 : 2);
}
__device__ __forceinline__ uint32_t smem_u32(const void* p) {
    uint32_t a;
    asm("{ .reg .u64 t; cvta.to.shared.u64 t, %1; cvt.u32.u64 %0, t; }" : "=r"(a) : "l"(p));
    return a;
}

// HMMA m16n8k16 row.col f32 += bf16*bf16
__device__ __forceinline__ void mma_bf16(float* d, const uint32_t* a, const uint32_t* b) {
    asm volatile(
        "mma.sync.aligned.m16n8k16.row.col.f32.bf16.bf16.f32 "
        "{%0,%1,%2,%3}, {%4,%5,%6,%7}, {%8,%9}, {%0,%1,%2,%3};"
        : "+f"(d[0]), "+f"(d[1]), "+f"(d[2]), "+f"(d[3])
        : "r"(a[0]), "r"(a[1]), "r"(a[2]), "r"(a[3]), "r"(b[0]), "r"(b[1]));
}
#define LDSM4(r, addr) \
    asm volatile("ldmatrix.sync.aligned.m8n8.x4.shared.b16 {%0,%1,%2,%3}, [%4];" \
        : "=r"((r)[0]), "=r"((r)[1]), "=r"((r)[2]), "=r"((r)[3]) : "r"(addr))

__device__ __forceinline__ void split_bf16(float v, unsigned short& h, unsigned short& l) {
    __nv_bfloat16 hb = __float2bfloat16_rn(v);
    __nv_bfloat16 lb = __float2bfloat16_rn(v - __bfloat162float(hb));
    h = __bfloat16_as_ushort(hb);
    l = __bfloat16_as_ushort(lb);
}

// =============================== k_gemm (R10) ===============================
#define ASTR 104
#define ROWB 208
#define AH_OFF 0
#define AL_OFF 26624
#define BH_OFF 53248
#define BL_OFF 73216
#define SMEM_DYN 93184

__global__ __launch_bounds__(256) void k_gemm(
    const float* __restrict__ in,    // [NTOK][96]
    const float* __restrict__ wmat,  // [96][wstride]
    const float* __restrict__ bias,  // [wstride]
    float* __restrict__ outp,        // [NTOK][wstride]
    int wstride, int nwhich, float scale0)
{
    extern __shared__ char smem[];
    unsigned short* AH = (unsigned short*)(smem + AH_OFF);
    unsigned short* AL = (unsigned short*)(smem + AL_OFF);
    unsigned short* BH = (unsigned short*)(smem + BH_OFF);
    unsigned short* BL = (unsigned short*)(smem + BL_OFF);

    const int tid  = threadIdx.x;
    const int wrp  = tid >> 5;
    const int lane = tid & 31;
    const int grp  = lane >> 2;
    const int tig  = lane & 3;
    const size_t m0 = (size_t)blockIdx.x * 128;

    const uint32_t sbase = smem_u32(smem);
    const uint32_t aoff =
        (uint32_t)(wrp * 16 + (lane & 15)) * ROWB + ((lane & 16) ? 16u : 0u);
    const uint32_t aAddrH = sbase + AH_OFF + aoff;
    const uint32_t aAddrL = sbase + AL_OFF + aoff;
    const uint32_t boff =
        (uint32_t)((lane & 7) + ((lane & 16) ? 8 : 0)) * ROWB + ((lane & 8) ? 16u : 0u);
    const uint32_t bAddrH = sbase + BH_OFF + boff;
    const uint32_t bAddrL = sbase + BL_OFF + boff;

    for (int u = tid; u < 128 * 24; u += 256) {
        int r = u / 24, f4 = u % 24;
        float4 v = *(const float4*)&in[(m0 + r) * 96 + f4 * 4];
        float vv[4] = {v.x, v.y, v.z, v.w};
        ull hh = 0, ll = 0;
        #pragma unroll
        for (int e = 0; e < 4; e++) {
            unsigned short h, l;
            split_bf16(vv[e], h, l);
            hh |= (ull)h << (16 * e);
            ll |= (ull)l << (16 * e);
        }
        *(ull*)&AH[r * ASTR + f4 * 4] = hh;
        *(ull*)&AL[r * ASTR + f4 * 4] = ll;
    }

    for (int which = 0; which < nwhich; which++) {
        __syncthreads();
        for (int u = tid; u < 96 * 24; u += 256) {
            int k = u / 24, f4 = u % 24;
            float4 v = __ldg((const float4*)&wmat[(size_t)k * wstride + which * 96 + f4 * 4]);
            float vv[4] = {v.x, v.y, v.z, v.w};
            #pragma unroll
            for (int e = 0; e < 4; e++) {
                int n = f4 * 4 + e;
                unsigned short h, l;
                split_bf16(vv[e], h, l);
                BH[n * ASTR + k] = h;
                BL[n * ASTR + k] = l;
            }
        }
        __syncthreads();

        float acc[12][4] = {};
        #pragma unroll
        for (int ks = 0; ks < 6; ks++) {
            uint32_t ah[4], al[4];
            LDSM4(ah, aAddrH + ks * 32);
            LDSM4(al, aAddrL + ks * 32);
            #pragma unroll
            for (int p = 0; p < 6; p++) {
                uint32_t bh[4], bl[4];
                const uint32_t bo = (uint32_t)(p * 16 * ROWB + ks * 32);
                LDSM4(bh, bAddrH + bo);
                LDSM4(bl, bAddrL + bo);
                mma_bf16(acc[2 * p],     ah, bh);
                mma_bf16(acc[2 * p],     ah, bl);
                mma_bf16(acc[2 * p],     al, bh);
                mma_bf16(acc[2 * p + 1], ah, bh + 2);
                mma_bf16(acc[2 * p + 1], ah, bl + 2);
                mma_bf16(acc[2 * p + 1], al, bh + 2);
            }
        }

        const float sc = (which == 0) ? scale0 : 1.0f;
        const size_t row0 = m0 + wrp * 16 + grp;
        #pragma unroll
        for (int nt = 0; nt < 12; nt++) {
            int col = which * 96 + nt * 8 + tig * 2;
            float2 bv = __ldg((const float2*)&bias[col]);
            float2 o0, o1;
            o0.x = (acc[nt][0] + bv.x) * sc; o0.y = (acc[nt][1] + bv.y) * sc;
            o1.x = (acc[nt][2] + bv.x) * sc; o1.y = (acc[nt][3] + bv.y) * sc;
            *(float2*)&outp[row0 * wstride + col] = o0;
            *(float2*)&outp[(row0 + 8) * wstride + col] = o1;
        }
    }
}

// =============================== k_attn (HMMA) ==============================
// smem byte offsets (static array, ~42.2KB)
//  region A (20480B): QH 0..5120, QL ..10240, KH ..15360, KL ..20480
//    after S-mma it is reused as: PH 0..9216, PL 9216..18432
//  VTH 20480 (4608), VTL 25088 (4608)
//  S   29696: f32 [52][58] = 12064  -> 41760
//  TOK 41760 (208), CODE 41968 (208) -> 42176
#define QK_STR 40     // ushorts per row (80B)
#define P_STR  72     // ushorts per row (144B)
#define S_STR  58
#define OFF_QH 0
#define OFF_QL 5120
#define OFF_KH 10240
#define OFF_KL 15360
#define OFF_PH 0
#define OFF_PL 9216
#define OFF_VTH 20480
#define OFF_VTL 25088
#define OFF_S  29696
#define OFF_TOK 41760
#define OFF_CODE 41968
#define SMEM_ATTN 42176

__global__ __launch_bounds__(128) void k_attn(const float* __restrict__ bias_table)
{
    __shared__ __align__(16) char sm[SMEM_ATTN];

    const int bw   = blockIdx.x;
    const int head = blockIdx.y;
    const int tid  = threadIdx.x;
    const int wrp  = tid >> 5;
    const int lane = tid & 31;
    const int grp  = lane >> 2;
    const int tig  = lane & 3;

    int* tokv = (int*)(sm + OFF_TOK);
    int* code = (int*)(sm + OFF_CODE);
    unsigned short* QH = (unsigned short*)(sm + OFF_QH);
    unsigned short* QL = (unsigned short*)(sm + OFF_QL);
    unsigned short* KH = (unsigned short*)(sm + OFF_KH);
    unsigned short* KL = (unsigned short*)(sm + OFF_KL);
    unsigned short* PH = (unsigned short*)(sm + OFF_PH);
    unsigned short* PL = (unsigned short*)(sm + OFF_PL);
    unsigned short* VTH = (unsigned short*)(sm + OFF_VTH);
    unsigned short* VTL = (unsigned short*)(sm + OFF_VTL);
    float* S = (float*)(sm + OFF_S);

    {
        int b = bw >> 8, w = bw & 255;
        int wy = w >> 4, wx = w & 15;
        for (int n = tid; n < N_; n += 128) {
            int i = n / 7, j = n % 7;
            int gy = wy * 7 + i + SS_; if (gy >= HW_) gy -= HW_;
            int gx = wx * 7 + j + SS_; if (gx >= HW_) gx -= HW_;
            tokv[n] = (b * HW_ + gy) * HW_ + gx;
            code[n] = rcode(gy) * 3 + rcode(gx);
        }
        // zero V^T pad columns m=49..63 (rows d=0..31)
        for (int u = tid; u < 32 * 15; u += 128) {
            int d = u / 15, c = 49 + u % 15;
            VTH[d * P_STR + c] = 0;
            VTL[d * P_STR + c] = 0;
        }
    }
    __syncthreads();

    // gather q/k/v rows (coalesced 128B per row), convert to bf16 hi/lo
    for (int u = tid; u < N_ * HD_; u += 128) {
        int n = u >> 5, d = u & 31;
        const float* row = g_qkv + (size_t)tokv[n] * 288 + head * HD_ + d;
        unsigned short h, l;
        split_bf16(row[0], h, l);             // q
        QH[n * QK_STR + d] = h;  QL[n * QK_STR + d] = l;
        split_bf16(row[96], h, l);            // k
        KH[n * QK_STR + d] = h;  KL[n * QK_STR + d] = l;
        split_bf16(row[192], h, l);           // v (transposed: [d][m])
        VTH[d * P_STR + n] = h;  VTL[d * P_STR + n] = l;
    }
    __syncthreads();

    // ---- S = q @ k^T (49x49 pad 64x64, K=32), 3-term bf16 split ----
    {
        const uint32_t sb = smem_u32(sm);
        const uint32_t ao = (uint32_t)(wrp * 16 + (lane & 15)) * 80 + ((lane & 16) ? 16u : 0u);
        const uint32_t aH = sb + OFF_QH + ao, aL = sb + OFF_QL + ao;
        const uint32_t bo = (uint32_t)((lane & 7) + ((lane & 16) ? 8 : 0)) * 80 + ((lane & 8) ? 16u : 0u);
        const uint32_t bH = sb + OFF_KH + bo, bL = sb + OFF_KL + bo;

        float acc[8][4] = {};
        #pragma unroll
        for (int ks = 0; ks < 2; ks++) {
            uint32_t ah[4], al[4];
            LDSM4(ah, aH + ks * 32);
            LDSM4(al, aL + ks * 32);
            #pragma unroll
            for (int p = 0; p < 4; p++) {
                uint32_t kh[4], kl[4];
                const uint32_t po = (uint32_t)(p * 16 * 80 + ks * 32);
                LDSM4(kh, bH + po);
                LDSM4(kl, bL + po);
                mma_bf16(acc[2 * p],     ah, kh);
                mma_bf16(acc[2 * p],     ah, kl);
                mma_bf16(acc[2 * p],     al, kh);
                mma_bf16(acc[2 * p + 1], ah, kh + 2);
                mma_bf16(acc[2 * p + 1], ah, kl + 2);
                mma_bf16(acc[2 * p + 1], al, kh + 2);
            }
        }
        const int r0 = wrp * 16 + grp, r1 = r0 + 8;
        #pragma unroll
        for (int nt = 0; nt < 7; nt++) {
            int col = nt * 8 + tig * 2;
            if (r0 < N_) { S[r0 * S_STR + col] = acc[nt][0]; S[r0 * S_STR + col + 1] = acc[nt][1]; }
            if (r1 < N_) { S[r1 * S_STR + col] = acc[nt][2]; S[r1 * S_STR + col + 1] = acc[nt][3]; }
        }
    }
    __syncthreads();

    // ---- softmax rows (bias + analytic mask); write P as bf16 hi/lo ----
    for (int r = wrp; r < N_; r += 4) {
        int i1 = r / 7, j1 = r % 7, c1 = code[r];
        int m1 = lane, m2 = lane + 32;
        int i2 = m1 / 7, j2 = m1 % 7;
        float b1 = __ldg(&bias_table[((i1 - i2 + 6) * 13 + (j1 - j2 + 6)) * NH_ + head]);
        float v1 = S[r * S_STR + m1] + b1 + (code[m1] == c1 ? 0.0f : -1e9f);
        float v2 = -1e30f;
        if (m2 < N_) {
            int i3 = m2 / 7, j3 = m2 % 7;
            float b2 = __ldg(&bias_table[((i1 - i3 + 6) * 13 + (j1 - j3 + 6)) * NH_ + head]);
            v2 = S[r * S_STR + m2] + b2 + (code[m2] == c1 ? 0.0f : -1e9f);
        }
        float mx = fmaxf(v1, v2);
        #pragma unroll
        for (int o = 16; o > 0; o >>= 1) mx = fmaxf(mx, __shfl_xor_sync(0xffffffffu, mx, o));
        float e1 = __expf(v1 - mx);
        float e2 = (m2 < N_) ? __expf(v2 - mx) : 0.0f;
        float sum = e1 + e2;
        #pragma unroll
        for (int o = 16; o > 0; o >>= 1) sum += __shfl_xor_sync(0xffffffffu, sum, o);
        float inv = 1.0f / sum;
        unsigned short h, l;
        split_bf16(e1 * inv, h, l);
        PH[r * P_STR + m1] = h;  PL[r * P_STR + m1] = l;
        if (m2 < N_) {
            split_bf16(e2 * inv, h, l);
            PH[r * P_STR + m2] = h;  PL[r * P_STR + m2] = l;
        } else {
            PH[r * P_STR + m2] = 0;  PL[r * P_STR + m2] = 0;  // pad cols 49..63
        }
    }
    __syncthreads();

    // ---- O = P @ V (49x32, K=49 pad 64), 3-term bf16 split ----
    {
        const uint32_t sb = smem_u32(sm);
        const uint32_t ao = (uint32_t)(wrp * 16 + (lane & 15)) * 144 + ((lane & 16) ? 16u : 0u);
        const uint32_t aH = sb + OFF_PH + ao, aL = sb + OFF_PL + ao;
        const uint32_t bo = (uint32_t)((lane & 7) + ((lane & 16) ? 8 : 0)) * 144 + ((lane & 8) ? 16u : 0u);
        const uint32_t bH = sb + OFF_VTH + bo, bL = sb + OFF_VTL + bo;

        float acc[4][4] = {};
        #pragma unroll
        for (int ks = 0; ks < 4; ks++) {
            uint32_t ph[4], pl[4];
            LDSM4(ph, aH + ks * 32);
            LDSM4(pl, aL + ks * 32);
            #pragma unroll
            for (int p = 0; p < 2; p++) {
                uint32_t vh[4], vl[4];
                const uint32_t po = (uint32_t)(p * 16 * 144 + ks * 32);
                LDSM4(vh, bH + po);
                LDSM4(vl, bL + po);
                mma_bf16(acc[2 * p],     ph, vh);
                mma_bf16(acc[2 * p],     ph, vl);
                mma_bf16(acc[2 * p],     pl, vh);
                mma_bf16(acc[2 * p + 1], ph, vh + 2);
                mma_bf16(acc[2 * p + 1], ph, vl + 2);
                mma_bf16(acc[2 * p + 1], pl, vh + 2);
            }
        }
        const int r0 = wrp * 16 + grp, r1 = r0 + 8;
        #pragma unroll
        for (int nt = 0; nt < 4; nt++) {
            int d0 = nt * 8 + tig * 2;
            if (r0 < N_) {
                float2 o; o.x = acc[nt][0]; o.y = acc[nt][1];
                *(float2*)&g_y[(size_t)tokv[r0] * 96 + head * HD_ + d0] = o;
            }
            if (r1 < N_) {
                float2 o; o.x = acc[nt][2]; o.y = acc[nt][3];
                *(float2*)&g_y[(size_t)tokv[r1] * 96 + head * HD_ + d0] = o;
            }
        }
    }
}

// ---------------------------------------------------------------------------
extern "C" void kernel_launch(void* const* d_in, const int* in_sizes, int n_in,
                              void* d_out, int out_size)
{
    (void)in_sizes; (void)n_in; (void)out_size;
    const float* x          = (const float*)d_in[0];
    const float* qkv_w      = (const float*)d_in[1];
    const float* qkv_b      = (const float*)d_in[2];
    const float* proj_w     = (const float*)d_in[3];
    const float* proj_b     = (const float*)d_in[4];
    const float* bias_table = (const float*)d_in[5];
    float* out = (float*)d_out;

    void *pqkv = nullptr, *py = nullptr;
    cudaGetSymbolAddress(&pqkv, g_qkv);
    cudaGetSymbolAddress(&py, g_y);
    static bool attr_done = false;
    if (!attr_done) {
        cudaFuncSetAttribute(k_gemm, cudaFuncAttributeMaxDynamicSharedMemorySize, SMEM_DYN);
        attr_done = true;
    }

    // QKV: [NTOK,96] @ [96,288] (+bias, q-scale), token-natural
    k_gemm<<<MTILES, 256, SMEM_DYN>>>(x, qkv_w, qkv_b, (float*)pqkv,
                                      288, 3, 0.17677669529663687f);
    // attention (token-indexed gather/scatter, HMMA)
    k_attn<<<dim3(BNW, NH_), 128>>>(bias_table);
    // proj: [NTOK,96] @ [96,96] (+bias) -> out (token-natural)
    k_gemm<<<MTILES, 256, SMEM_DYN>>>((const float*)py, proj_w, proj_b, out,
                                      96, 1, 1.0f);
}

// round 13
// speedup vs baseline: 1.9512x; 1.3334x over previous
#include <cuda_runtime.h>
#include <cuda_bf16.h>
#include <cstdint>

// Swin shifted-window MSA: B=32, H=W=112, C=96, ws=7, ss=3, nh=3, hd=32
// Round 12: kill transposing smem writes (16-way-conflict scalar STS) by
// storing B/V natural row-major and using ldmatrix.x4.trans at read time.
// Gather in k_attn now float4 LDG + packed 64-bit STS.

#define WS_ 7
#define SS_ 3
#define NH_ 3
#define HD_ 32
#define C_  96
#define N_  49
#define HW_ 112
#define BNW 8192
#define NTOK 401408          // 32*112*112 = 3136 * 128
#define MTILES 3136

typedef unsigned long long ull;

// scratch (static device globals; no allocation anywhere)
__device__ float g_qkv[(size_t)NTOK * 288];  // [token][which*96 + c]
__device__ float g_y[(size_t)NTOK * 96];     // [token][c]

__device__ __forceinline__ int rcode(int h) {
    return h < (HW_ - WS_) ? 0 : (h < (HW_ - SS_) ? 1 : 2);
}
__device__ __forceinline__ uint32_t smem_u32(const void* p) {
    uint32_t a;
    asm("{ .reg .u64 t; cvta.to.shared.u64 t, %1; cvt.u32.u64 %0, t; }" : "=r"(a) : "l"(p));
    return a;
}

// HMMA m16n8k16 row.col f32 += bf16*bf16
__device__ __forceinline__ void mma_bf16(float* d, const uint32_t* a, const uint32_t* b) {
    asm volatile(
        "mma.sync.aligned.m16n8k16.row.col.f32.bf16.bf16.f32 "
        "{%0,%1,%2,%3}, {%4,%5,%6,%7}, {%8,%9}, {%0,%1,%2,%3};"
        : "+f"(d[0]), "+f"(d[1]), "+f"(d[2]), "+f"(d[3])
        : "r"(a[0]), "r"(a[1]), "r"(a[2]), "r"(a[3]), "r"(b[0]), "r"(b[1]));
}
#define LDSM4(r, addr) \
    asm volatile("ldmatrix.sync.aligned.m8n8.x4.shared.b16 {%0,%1,%2,%3}, [%4];" \
        : "=r"((r)[0]), "=r"((r)[1]), "=r"((r)[2]), "=r"((r)[3]) : "r"(addr))
#define LDSM4T(r, addr) \
    asm volatile("ldmatrix.sync.aligned.m8n8.x4.trans.shared.b16 {%0,%1,%2,%3}, [%4];" \
        : "=r"((r)[0]), "=r"((r)[1]), "=r"((r)[2]), "=r"((r)[3]) : "r"(addr))

__device__ __forceinline__ void split_bf16(float v, unsigned short& h, unsigned short& l) {
    __nv_bfloat16 hb = __float2bfloat16_rn(v);
    __nv_bfloat16 lb = __float2bfloat16_rn(v - __bfloat162float(hb));
    h = __bfloat16_as_ushort(hb);
    l = __bfloat16_as_ushort(lb);
}
__device__ __forceinline__ void split4(float4 v, ull& hh, ull& ll) {
    float vv[4] = {v.x, v.y, v.z, v.w};
    hh = 0; ll = 0;
    #pragma unroll
    for (int e = 0; e < 4; e++) {
        unsigned short h, l;
        split_bf16(vv[e], h, l);
        hh |= (ull)h << (16 * e);
        ll |= (ull)l << (16 * e);
    }
}

// =============================== k_gemm ====================================
#define ASTR 104
#define ROWB 208
#define AH_OFF 0
#define AL_OFF 26624
#define BH_OFF 53248
#define BL_OFF 73216
#define SMEM_DYN 93184

__global__ __launch_bounds__(256) void k_gemm(
    const float* __restrict__ in,    // [NTOK][96]
    const float* __restrict__ wmat,  // [96][wstride]
    const float* __restrict__ bias,  // [wstride]
    float* __restrict__ outp,        // [NTOK][wstride]
    int wstride, int nwhich, float scale0)
{
    extern __shared__ char smem[];
    unsigned short* AH = (unsigned short*)(smem + AH_OFF);
    unsigned short* AL = (unsigned short*)(smem + AL_OFF);
    unsigned short* BH = (unsigned short*)(smem + BH_OFF);
    unsigned short* BL = (unsigned short*)(smem + BL_OFF);

    const int tid  = threadIdx.x;
    const int wrp  = tid >> 5;
    const int lane = tid & 31;
    const int grp  = lane >> 2;
    const int tig  = lane & 3;
    const size_t m0 = (size_t)blockIdx.x * 128;

    const uint32_t sbase = smem_u32(smem);
    // A (row-major rows m): normal ldmatrix
    const uint32_t aoff =
        (uint32_t)(wrp * 16 + (lane & 15)) * ROWB + ((lane & 16) ? 16u : 0u);
    const uint32_t aAddrH = sbase + AH_OFF + aoff;
    const uint32_t aAddrL = sbase + AL_OFF + aoff;
    // B stored [k][n]: trans ldmatrix; rows k = (lane&15), col half by bit4
    const uint32_t boff =
        (uint32_t)(lane & 15) * ROWB + ((lane & 16) ? 16u : 0u);
    const uint32_t bAddrH = sbase + BH_OFF + boff;
    const uint32_t bAddrL = sbase + BL_OFF + boff;

    // ---- A fill: 128 x 96 f32 -> bf16 hi/lo (packed 64-bit stores) ----
    for (int u = tid; u < 128 * 24; u += 256) {
        int r = u / 24, f4 = u % 24;
        float4 v = *(const float4*)&in[(m0 + r) * 96 + f4 * 4];
        ull hh, ll; split4(v, hh, ll);
        *(ull*)&AH[r * ASTR + f4 * 4] = hh;
        *(ull*)&AL[r * ASTR + f4 * 4] = ll;
    }

    for (int which = 0; which < nwhich; which++) {
        __syncthreads();
        // ---- B fill NATURAL [k][n] layout (packed 64-bit stores) ----
        for (int u = tid; u < 96 * 24; u += 256) {
            int k = u / 24, f4 = u % 24;
            float4 v = __ldg((const float4*)&wmat[(size_t)k * wstride + which * 96 + f4 * 4]);
            ull hh, ll; split4(v, hh, ll);
            *(ull*)&BH[k * ASTR + f4 * 4] = hh;
            *(ull*)&BL[k * ASTR + f4 * 4] = ll;
        }
        __syncthreads();

        // ---- compute: warp computes 16 x 96, K=96, 3-term bf16 split ----
        float acc[12][4] = {};
        #pragma unroll
        for (int ks = 0; ks < 6; ks++) {
            uint32_t ah[4], al[4];
            LDSM4(ah, aAddrH + ks * 32);
            LDSM4(al, aAddrL + ks * 32);
            #pragma unroll
            for (int p = 0; p < 6; p++) {
                uint32_t bh[4], bl[4];
                const uint32_t bo = (uint32_t)(ks * 16 * ROWB + p * 32);
                LDSM4T(bh, bAddrH + bo);
                LDSM4T(bl, bAddrL + bo);
                mma_bf16(acc[2 * p],     ah, bh);
                mma_bf16(acc[2 * p],     ah, bl);
                mma_bf16(acc[2 * p],     al, bh);
                mma_bf16(acc[2 * p + 1], ah, bh + 2);
                mma_bf16(acc[2 * p + 1], ah, bl + 2);
                mma_bf16(acc[2 * p + 1], al, bh + 2);
            }
        }

        // ---- epilogue: bias + scale, direct stores ----
        const float sc = (which == 0) ? scale0 : 1.0f;
        const size_t row0 = m0 + wrp * 16 + grp;
        #pragma unroll
        for (int nt = 0; nt < 12; nt++) {
            int col = which * 96 + nt * 8 + tig * 2;
            float2 bv = __ldg((const float2*)&bias[col]);
            float2 o0, o1;
            o0.x = (acc[nt][0] + bv.x) * sc; o0.y = (acc[nt][1] + bv.y) * sc;
            o1.x = (acc[nt][2] + bv.x) * sc; o1.y = (acc[nt][3] + bv.y) * sc;
            *(float2*)&outp[row0 * wstride + col] = o0;
            *(float2*)&outp[(row0 + 8) * wstride + col] = o1;
        }
    }
}

// =============================== k_attn (HMMA) ==============================
// smem byte offsets (static array):
//  QH 0, QL 5120, KH 10240, KL 15360   (each 64 rows x 40 ushorts = 5120B)
//    after S-mma reused as: PH 0..9216, PL 9216..18432  ([64][72] ushorts)
//  VH 20480 (5120), VL 25600 (5120)    (V natural [m][d], 64 rows x 40)
//  S  30720: f32 [52][58] = 12064 -> 42784
//  TOK 42784, CODE 42992 -> 43200
#define QK_STR 40     // ushorts per row (80B)
#define P_STR  72     // ushorts per row (144B)
#define S_STR  58
#define OFF_QH 0
#define OFF_QL 5120
#define OFF_KH 10240
#define OFF_KL 15360
#define OFF_PH 0
#define OFF_PL 9216
#define OFF_VH 20480
#define OFF_VL 25600
#define OFF_S  30720
#define OFF_TOK 42784
#define OFF_CODE 42992
#define SMEM_ATTN 43200

__global__ __launch_bounds__(128) void k_attn(const float* __restrict__ bias_table)
{
    __shared__ __align__(16) char sm[SMEM_ATTN];

    const int bw   = blockIdx.x;
    const int head = blockIdx.y;
    const int tid  = threadIdx.x;
    const int wrp  = tid >> 5;
    const int lane = tid & 31;
    const int grp  = lane >> 2;
    const int tig  = lane & 3;

    int* tokv = (int*)(sm + OFF_TOK);
    int* code = (int*)(sm + OFF_CODE);
    unsigned short* QH = (unsigned short*)(sm + OFF_QH);
    unsigned short* QL = (unsigned short*)(sm + OFF_QL);
    unsigned short* KH = (unsigned short*)(sm + OFF_KH);
    unsigned short* KL = (unsigned short*)(sm + OFF_KL);
    unsigned short* PH = (unsigned short*)(sm + OFF_PH);
    unsigned short* PL = (unsigned short*)(sm + OFF_PL);
    unsigned short* VH = (unsigned short*)(sm + OFF_VH);
    unsigned short* VL = (unsigned short*)(sm + OFF_VL);
    float* S = (float*)(sm + OFF_S);

    {
        int b = bw >> 8, w = bw & 255;
        int wy = w >> 4, wx = w & 15;
        for (int n = tid; n < N_; n += 128) {
            int i = n / 7, j = n % 7;
            int gy = wy * 7 + i + SS_; if (gy >= HW_) gy -= HW_;
            int gx = wx * 7 + j + SS_; if (gx >= HW_) gx -= HW_;
            tokv[n] = (b * HW_ + gy) * HW_ + gx;
            code[n] = rcode(gy) * 3 + rcode(gx);
        }
        // zero V pad rows m=49..63 (avoid NaN x 0 in PV mma)
        for (int u = tid; u < 15 * 10; u += 128) {
            int r = 49 + u / 10, c = (u % 10) * 4;
            *(ull*)&VH[r * QK_STR + c] = 0;
            *(ull*)&VL[r * QK_STR + c] = 0;
        }
    }
    __syncthreads();

    // gather q/k/v rows: float4 LDG + packed 64-bit STS, natural layouts
    for (int u = tid; u < N_ * 8; u += 128) {
        int n = u >> 3, d0 = (u & 7) * 4;
        const float* row = g_qkv + (size_t)tokv[n] * 288 + head * HD_ + d0;
        ull hh, ll;
        split4(*(const float4*)row, hh, ll);          // q
        *(ull*)&QH[n * QK_STR + d0] = hh; *(ull*)&QL[n * QK_STR + d0] = ll;
        split4(*(const float4*)(row + 96), hh, ll);   // k
        *(ull*)&KH[n * QK_STR + d0] = hh; *(ull*)&KL[n * QK_STR + d0] = ll;
        split4(*(const float4*)(row + 192), hh, ll);  // v (natural [m][d])
        *(ull*)&VH[n * QK_STR + d0] = hh; *(ull*)&VL[n * QK_STR + d0] = ll;
    }
    __syncthreads();

    // ---- S = q @ k^T (49x49 pad 64x64, K=32), 3-term bf16 split ----
    {
        const uint32_t sb = smem_u32(sm);
        const uint32_t ao = (uint32_t)(wrp * 16 + (lane & 15)) * 80 + ((lane & 16) ? 16u : 0u);
        const uint32_t aH = sb + OFF_QH + ao, aL = sb + OFF_QL + ao;
        const uint32_t bo = (uint32_t)((lane & 7) + ((lane & 16) ? 8 : 0)) * 80 + ((lane & 8) ? 16u : 0u);
        const uint32_t bH = sb + OFF_KH + bo, bL = sb + OFF_KL + bo;

        float acc[8][4] = {};
        #pragma unroll
        for (int ks = 0; ks < 2; ks++) {
            uint32_t ah[4], al[4];
            LDSM4(ah, aH + ks * 32);
            LDSM4(al, aL + ks * 32);
            #pragma unroll
            for (int p = 0; p < 4; p++) {
                uint32_t kh[4], kl[4];
                const uint32_t po = (uint32_t)(p * 16 * 80 + ks * 32);
                LDSM4(kh, bH + po);
                LDSM4(kl, bL + po);
                mma_bf16(acc[2 * p],     ah, kh);
                mma_bf16(acc[2 * p],     ah, kl);
                mma_bf16(acc[2 * p],     al, kh);
                mma_bf16(acc[2 * p + 1], ah, kh + 2);
                mma_bf16(acc[2 * p + 1], ah, kl + 2);
                mma_bf16(acc[2 * p + 1], al, kh + 2);
            }
        }
        const int r0 = wrp * 16 + grp, r1 = r0 + 8;
        #pragma unroll
        for (int nt = 0; nt < 7; nt++) {
            int col = nt * 8 + tig * 2;
            if (r0 < N_) { S[r0 * S_STR + col] = acc[nt][0]; S[r0 * S_STR + col + 1] = acc[nt][1]; }
            if (r1 < N_) { S[r1 * S_STR + col] = acc[nt][2]; S[r1 * S_STR + col + 1] = acc[nt][3]; }
        }
    }
    __syncthreads();

    // ---- softmax rows (bias + analytic mask); write P as bf16 hi/lo ----
    for (int r = wrp; r < N_; r += 4) {
        int i1 = r / 7, j1 = r % 7, c1 = code[r];
        int m1 = lane, m2 = lane + 32;
        int i2 = m1 / 7, j2 = m1 % 7;
        float b1 = __ldg(&bias_table[((i1 - i2 + 6) * 13 + (j1 - j2 + 6)) * NH_ + head]);
        float v1 = S[r * S_STR + m1] + b1 + (code[m1] == c1 ? 0.0f : -1e9f);
        float v2 = -1e30f;
        if (m2 < N_) {
            int i3 = m2 / 7, j3 = m2 % 7;
            float b2 = __ldg(&bias_table[((i1 - i3 + 6) * 13 + (j1 - j3 + 6)) * NH_ + head]);
            v2 = S[r * S_STR + m2] + b2 + (code[m2] == c1 ? 0.0f : -1e9f);
        }
        float mx = fmaxf(v1, v2);
        #pragma unroll
        for (int o = 16; o > 0; o >>= 1) mx = fmaxf(mx, __shfl_xor_sync(0xffffffffu, mx, o));
        float e1 = __expf(v1 - mx);
        float e2 = (m2 < N_) ? __expf(v2 - mx) : 0.0f;
        float sum = e1 + e2;
        #pragma unroll
        for (int o = 16; o > 0; o >>= 1) sum += __shfl_xor_sync(0xffffffffu, sum, o);
        float inv = 1.0f / sum;
        unsigned short h, l;
        split_bf16(e1 * inv, h, l);
        PH[r * P_STR + m1] = h;  PL[r * P_STR + m1] = l;
        if (m2 < N_) {
            split_bf16(e2 * inv, h, l);
            PH[r * P_STR + m2] = h;  PL[r * P_STR + m2] = l;
        } else {
            PH[r * P_STR + m2] = 0;  PL[r * P_STR + m2] = 0;  // pad cols 49..63
        }
    }
    __syncthreads();

    // ---- O = P @ V (49x32, K=49 pad 64), V natural + trans ldmatrix ----
    {
        const uint32_t sb = smem_u32(sm);
        const uint32_t ao = (uint32_t)(wrp * 16 + (lane & 15)) * 144 + ((lane & 16) ? 16u : 0u);
        const uint32_t aH = sb + OFF_PH + ao, aL = sb + OFF_PL + ao;
        const uint32_t bo = (uint32_t)(lane & 15) * 80 + ((lane & 16) ? 16u : 0u);
        const uint32_t bH = sb + OFF_VH + bo, bL = sb + OFF_VL + bo;

        float acc[4][4] = {};
        #pragma unroll
        for (int ks = 0; ks < 4; ks++) {
            uint32_t ph[4], pl[4];
            LDSM4(ph, aH + ks * 32);
            LDSM4(pl, aL + ks * 32);
            #pragma unroll
            for (int p = 0; p < 2; p++) {
                uint32_t vh[4], vl[4];
                const uint32_t po = (uint32_t)(ks * 16 * 80 + p * 32);
                LDSM4T(vh, bH + po);
                LDSM4T(vl, bL + po);
                mma_bf16(acc[2 * p],     ph, vh);
                mma_bf16(acc[2 * p],     ph, vl);
                mma_bf16(acc[2 * p],     pl, vh);
                mma_bf16(acc[2 * p + 1], ph, vh + 2);
                mma_bf16(acc[2 * p + 1], ph, vl + 2);
                mma_bf16(acc[2 * p + 1], pl, vh + 2);
            }
        }
        const int r0 = wrp * 16 + grp, r1 = r0 + 8;
        #pragma unroll
        for (int nt = 0; nt < 4; nt++) {
            int d0 = nt * 8 + tig * 2;
            if (r0 < N_) {
                float2 o; o.x = acc[nt][0]; o.y = acc[nt][1];
                *(float2*)&g_y[(size_t)tokv[r0] * 96 + head * HD_ + d0] = o;
            }
            if (r1 < N_) {
                float2 o; o.x = acc[nt][2]; o.y = acc[nt][3];
                *(float2*)&g_y[(size_t)tokv[r1] * 96 + head * HD_ + d0] = o;
            }
        }
    }
}

// ---------------------------------------------------------------------------
extern "C" void kernel_launch(void* const* d_in, const int* in_sizes, int n_in,
                              void* d_out, int out_size)
{
    (void)in_sizes; (void)n_in; (void)out_size;
    const float* x          = (const float*)d_in[0];
    const float* qkv_w      = (const float*)d_in[1];
    const float* qkv_b      = (const float*)d_in[2];
    const float* proj_w     = (const float*)d_in[3];
    const float* proj_b     = (const float*)d_in[4];
    const float* bias_table = (const float*)d_in[5];
    float* out = (float*)d_out;

    void *pqkv = nullptr, *py = nullptr;
    cudaGetSymbolAddress(&pqkv, g_qkv);
    cudaGetSymbolAddress(&py, g_y);
    static bool attr_done = false;
    if (!attr_done) {
        cudaFuncSetAttribute(k_gemm, cudaFuncAttributeMaxDynamicSharedMemorySize, SMEM_DYN);
        attr_done = true;
    }

    // QKV: [NTOK,96] @ [96,288] (+bias, q-scale), token-natural
    k_gemm<<<MTILES, 256, SMEM_DYN>>>(x, qkv_w, qkv_b, (float*)pqkv,
                                      288, 3, 0.17677669529663687f);
    // attention (token-indexed gather/scatter, HMMA)
    k_attn<<<dim3(BNW, NH_), 128>>>(bias_table);
    // proj: [NTOK,96] @ [96,96] (+bias) -> out (token-natural)
    k_gemm<<<MTILES, 256, SMEM_DYN>>>((const float*)py, proj_w, proj_b, out,
                                      96, 1, 1.0f);
}

// round 14
// speedup vs baseline: 2.0690x; 1.0604x over previous
#include <cuda_runtime.h>
#include <cuda_bf16.h>
#include <cstdint>

// Swin shifted-window MSA: B=32, H=W=112, C=96, ws=7, ss=3, nh=3, hd=32
// Round 13: FULL FUSION. One block = one window: gather x -> QKV GEMM ->
// attention (3 heads) -> proj -> scatter out, all in smem. Eliminates the
// g_qkv (462MB x2) and g_y (154MB x2) DRAM round trips. Weights prepacked
// once per launch into bf16 hi/lo per-head tiles (k_prepack).
// All HMMA fragment paths identical to the validated R12 kernels.

#define WS_ 7
#define SS_ 3
#define NH_ 3
#define HD_ 32
#define C_  96
#define N_  49
#define HW_ 112
#define BNW 8192

typedef unsigned long long ull;

// prepacked weights (bf16 hi/lo), padded stride 104 ushorts (208B rows)
__device__ __align__(16) unsigned short g_wqkv[3 * 2 * 96 * 104];  // [head][s][96k][104n]
__device__ __align__(16) unsigned short g_wproj[3 * 2 * 32 * 104]; // [head][s][32k][104n]

__device__ __forceinline__ int rcode(int h) {
    return h < (HW_ - WS_) ? 0 : (h < (HW_ - SS_) ? 1 : 2);
}
__device__ __forceinline__ uint32_t smem_u32(const void* p) {
    uint32_t a;
    asm("{ .reg .u64 t; cvta.to.shared.u64 t, %1; cvt.u32.u64 %0, t; }" : "=r"(a) : "l"(p));
    return a;
}
__device__ __forceinline__ void mma_bf16(float* d, const uint32_t* a, const uint32_t* b) {
    asm volatile(
        "mma.sync.aligned.m16n8k16.row.col.f32.bf16.bf16.f32 "
        "{%0,%1,%2,%3}, {%4,%5,%6,%7}, {%8,%9}, {%0,%1,%2,%3};"
        : "+f"(d[0]), "+f"(d[1]), "+f"(d[2]), "+f"(d[3])
        : "r"(a[0]), "r"(a[1]), "r"(a[2]), "r"(a[3]), "r"(b[0]), "r"(b[1]));
}
#define LDSM4(r, addr) \
    asm volatile("ldmatrix.sync.aligned.m8n8.x4.shared.b16 {%0,%1,%2,%3}, [%4];" \
        : "=r"((r)[0]), "=r"((r)[1]), "=r"((r)[2]), "=r"((r)[3]) : "r"(addr))
#define LDSM4T(r, addr) \
    asm volatile("ldmatrix.sync.aligned.m8n8.x4.trans.shared.b16 {%0,%1,%2,%3}, [%4];" \
        : "=r"((r)[0]), "=r"((r)[1]), "=r"((r)[2]), "=r"((r)[3]) : "r"(addr))

__device__ __forceinline__ void split_bf16(float v, unsigned short& h, unsigned short& l) {
    __nv_bfloat16 hb = __float2bfloat16_rn(v);
    __nv_bfloat16 lb = __float2bfloat16_rn(v - __bfloat162float(hb));
    h = __bfloat16_as_ushort(hb);
    l = __bfloat16_as_ushort(lb);
}
__device__ __forceinline__ void split4(float4 v, ull& hh, ull& ll) {
    float vv[4] = {v.x, v.y, v.z, v.w};
    hh = 0; ll = 0;
    #pragma unroll
    for (int e = 0; e < 4; e++) {
        unsigned short h, l;
        split_bf16(vv[e], h, l);
        hh |= (ull)h << (16 * e);
        ll |= (ull)l << (16 * e);
    }
}
__device__ __forceinline__ uint32_t pack_split2(float a, float b, uint32_t& lo) {
    unsigned short h0, l0, h1, l1;
    split_bf16(a, h0, l0);
    split_bf16(b, h1, l1);
    lo = (uint32_t)l0 | ((uint32_t)l1 << 16);
    return (uint32_t)h0 | ((uint32_t)h1 << 16);
}

// ---------------------------------------------------------------------------
// Prepack: qkv_w/proj_w -> bf16 hi/lo per-head tiles. grid=3, block=256.
// qkv tile n-layout: n<32:q(head), 32..63:k(head), 64..95:v(head)
// ---------------------------------------------------------------------------
__global__ __launch_bounds__(256) void k_prepack(
    const float* __restrict__ qkv_w, const float* __restrict__ proj_w)
{
    const int head = blockIdx.x, tid = threadIdx.x;
    for (int u = tid; u < 96 * 24; u += 256) {
        int k = u / 24, n = (u % 24) * 4;
        int strip = n >> 5, wi = n & 31;
        float4 v = *(const float4*)&qkv_w[k * 288 + strip * 96 + head * 32 + wi];
        ull hh, ll; split4(v, hh, ll);
        *(ull*)&g_wqkv[((head * 2 + 0) * 96 + k) * 104 + n] = hh;
        *(ull*)&g_wqkv[((head * 2 + 1) * 96 + k) * 104 + n] = ll;
    }
    for (int u = tid; u < 32 * 24; u += 256) {
        int k = u / 24, n = (u % 24) * 4;
        float4 v = *(const float4*)&proj_w[(head * 32 + k) * 96 + n];
        ull hh, ll; split4(v, hh, ll);
        *(ull*)&g_wproj[((head * 2 + 0) * 32 + k) * 104 + n] = hh;
        *(ull*)&g_wproj[((head * 2 + 1) * 32 + k) * 104 + n] = ll;
    }
}

// ---------------------------------------------------------------------------
// Fused kernel. grid = BNW, block = 128 (4 warps, warp owns rows 16w..16w+15).
// ---------------------------------------------------------------------------
// smem layout (byte offsets, all 16B aligned)
#define XA_H  0        // A_x hi: 64 x 104 ushorts (208B rows) = 13312
#define XA_L  13312
#define BQ_H  26624    // qkv weights hi: 96 x 208 = 19968
#define BQ_L  46592
#define P_H   26624    // P hi overlays BQ: 64 x 144 = 9216
#define P_L   35840
#define BP_H  66560    // proj weights hi: 32 x 208 = 6656
#define BP_L  73216
#define Q_H   79872    // 64 x 80 = 5120
#define Q_L   84992
#define O_H   79872    // O overlays Q
#define O_L   84992
#define K_H   90112
#define K_L   95232
#define V_H   100352
#define V_L   105472
#define TOK_O 110592   // int[64]
#define CODE_O 110848  // int[64]
#define SMEM_FUSED 111104

__global__ __launch_bounds__(128) void k_fused(
    const float* __restrict__ x,
    const float* __restrict__ qkv_b,
    const float* __restrict__ proj_b,
    const float* __restrict__ bias_table,
    float* __restrict__ out)
{
    extern __shared__ __align__(16) char sm[];
    const int tid  = threadIdx.x;
    const int wrp  = tid >> 5;
    const int lane = tid & 31;
    const int grp  = lane >> 2;
    const int tig  = lane & 3;
    const int bw   = blockIdx.x;

    int* tokv = (int*)(sm + TOK_O);
    int* code = (int*)(sm + CODE_O);

    // ---- window token map + region codes (64 entries, pad finite) ----
    {
        int b = bw >> 8, w = bw & 255;
        int wy = w >> 4, wx = w & 15;
        for (int n = tid; n < 64; n += 128) {
            if (n < N_) {
                int i = n / 7, j = n % 7;
                int gy = wy * 7 + i + SS_; if (gy >= HW_) gy -= HW_;
                int gx = wx * 7 + j + SS_; if (gx >= HW_) gx -= HW_;
                tokv[n] = (b * HW_ + gy) * HW_ + gx;
                code[n] = rcode(gy) * 3 + rcode(gx);
            } else { tokv[n] = 0; code[n] = -1; }
        }
        // zero A_x pad rows 49..63 (full 208B rows)
        for (int u = tid; u < 15 * 26; u += 128) {
            int r = 49 + u / 26, c = (u % 26) * 4;
            *(ull*)((unsigned short*)(sm + XA_H) + r * 104 + c) = 0;
            *(ull*)((unsigned short*)(sm + XA_L) + r * 104 + c) = 0;
        }
    }
    __syncthreads();

    // ---- gather x window -> A_x bf16 hi/lo ----
    for (int u = tid; u < N_ * 24; u += 128) {
        int n = u / 24, f4 = u % 24;
        float4 v = *(const float4*)&x[(size_t)tokv[n] * 96 + f4 * 4];
        ull hh, ll; split4(v, hh, ll);
        *(ull*)((unsigned short*)(sm + XA_H) + n * 104 + f4 * 4) = hh;
        *(ull*)((unsigned short*)(sm + XA_L) + n * 104 + f4 * 4) = ll;
    }

    // ---- per-lane ldmatrix addresses ----
    const uint32_t sb = smem_u32(sm);
    const uint32_t aoffA = (uint32_t)(wrp * 16 + (lane & 15)) * 208 + ((lane & 16) ? 16u : 0u);
    const uint32_t axH = sb + XA_H + aoffA, axL = sb + XA_L + aoffA;
    const uint32_t boffB = (uint32_t)(lane & 15) * 208 + ((lane & 16) ? 16u : 0u);
    const uint32_t bqH = sb + BQ_H + boffB, bqL = sb + BQ_L + boffB;
    const uint32_t bpH = sb + BP_H + boffB, bpL = sb + BP_L + boffB;
    const uint32_t toff = (uint32_t)(wrp * 16 + (lane & 15)) * 80 + ((lane & 16) ? 16u : 0u);
    const uint32_t qH = sb + Q_H + toff, qL = sb + Q_L + toff;
    const uint32_t oHa = sb + O_H + toff, oLa = sb + O_L + toff;
    const uint32_t koff = (uint32_t)((lane & 7) + ((lane & 16) ? 8 : 0)) * 80 + ((lane & 8) ? 16u : 0u);
    const uint32_t kH = sb + K_H + koff, kL = sb + K_L + koff;
    const uint32_t voff = (uint32_t)(lane & 15) * 80 + ((lane & 16) ? 16u : 0u);
    const uint32_t vH = sb + V_H + voff, vL = sb + V_L + voff;
    const uint32_t poff = (uint32_t)(wrp * 16 + (lane & 15)) * 144 + ((lane & 16) ? 16u : 0u);
    const uint32_t pHa = sb + P_H + poff, pLa = sb + P_L + poff;

    const int r0 = wrp * 16 + grp, r1 = r0 + 8;
    const int i1a = r0 / 7, j1a = r0 % 7;
    const int i1b = r1 / 7, j1b = r1 % 7;

    float pacc[12][4] = {};   // proj accumulator, held across heads

    for (int head = 0; head < 3; head++) {
        __syncthreads();  // prev head's P / Bproj reads complete
        // ---- weight fills: straight 16B copies of prepacked tiles ----
        {
            const uint4* sq = (const uint4*)(g_wqkv + head * 2 * 96 * 104);
            uint4* dqH = (uint4*)(sm + BQ_H);
            uint4* dqL = (uint4*)(sm + BQ_L);
            for (int u = tid; u < 1248; u += 128) { dqH[u] = sq[u]; dqL[u] = sq[1248 + u]; }
            const uint4* sp = (const uint4*)(g_wproj + head * 2 * 32 * 104);
            uint4* dpH = (uint4*)(sm + BP_H);
            uint4* dpL = (uint4*)(sm + BP_L);
            for (int u = tid; u < 416; u += 128) { dpH[u] = sp[u]; dpL[u] = sp[416 + u]; }
        }
        __syncthreads();

        // ---- QKV GEMM: [64x96] @ [96x96] (q|k|v strips for this head) ----
        {
            float acc[12][4] = {};
            #pragma unroll
            for (int ks = 0; ks < 6; ks++) {
                uint32_t ah[4], al[4];
                LDSM4(ah, axH + ks * 32);
                LDSM4(al, axL + ks * 32);
                #pragma unroll
                for (int p = 0; p < 6; p++) {
                    uint32_t bh[4], bl[4];
                    const uint32_t bo = (uint32_t)(ks * 16 * 208 + p * 32);
                    LDSM4T(bh, bqH + bo);
                    LDSM4T(bl, bqL + bo);
                    mma_bf16(acc[2 * p],     ah, bh);
                    mma_bf16(acc[2 * p],     ah, bl);
                    mma_bf16(acc[2 * p],     al, bh);
                    mma_bf16(acc[2 * p + 1], ah, bh + 2);
                    mma_bf16(acc[2 * p + 1], ah, bl + 2);
                    mma_bf16(acc[2 * p + 1], al, bh + 2);
                }
            }
            // epilogue: +bias (q scaled), split bf16 -> Q/K/V tiles
            #pragma unroll
            for (int nt = 0; nt < 12; nt++) {
                int strip = nt >> 2;               // 0=q 1=k 2=v
                int lc = (nt & 3) * 8 + tig * 2;   // col in 0..31
                int gcol = strip * 96 + head * 32 + lc;
                float2 bv = __ldg((const float2*)&qkv_b[gcol]);
                float sc = (strip == 0) ? 0.17677669529663687f : 1.0f;
                int tb_h = (strip == 0) ? Q_H : (strip == 1) ? K_H : V_H;
                int tb_l = (strip == 0) ? Q_L : (strip == 1) ? K_L : V_L;
                unsigned short* TH = (unsigned short*)(sm + tb_h);
                unsigned short* TL = (unsigned short*)(sm + tb_l);
                uint32_t lo, hi;
                hi = pack_split2((acc[nt][0] + bv.x) * sc, (acc[nt][1] + bv.y) * sc, lo);
                *(uint32_t*)&TH[r0 * 40 + lc] = hi;
                *(uint32_t*)&TL[r0 * 40 + lc] = lo;
                hi = pack_split2((acc[nt][2] + bv.x) * sc, (acc[nt][3] + bv.y) * sc, lo);
                *(uint32_t*)&TH[r1 * 40 + lc] = hi;
                *(uint32_t*)&TL[r1 * 40 + lc] = lo;
            }
        }
        __syncthreads();

        // ---- S = q @ k^T (64x64, K=32) ----
        float sacc[8][4] = {};
        #pragma unroll
        for (int ks = 0; ks < 2; ks++) {
            uint32_t ah[4], al[4];
            LDSM4(ah, qH + ks * 32);
            LDSM4(al, qL + ks * 32);
            #pragma unroll
            for (int p = 0; p < 4; p++) {
                uint32_t kh[4], kl[4];
                const uint32_t po = (uint32_t)(p * 16 * 80 + ks * 32);
                LDSM4(kh, kH + po);
                LDSM4(kl, kL + po);
                mma_bf16(sacc[2 * p],     ah, kh);
                mma_bf16(sacc[2 * p],     ah, kl);
                mma_bf16(sacc[2 * p],     al, kh);
                mma_bf16(sacc[2 * p + 1], ah, kh + 2);
                mma_bf16(sacc[2 * p + 1], ah, kl + 2);
                mma_bf16(sacc[2 * p + 1], al, kh + 2);
            }
        }

        // ---- softmax in registers (rows r0: regs 0/1, r1: regs 2/3) ----
        {
            unsigned short* PHs = (unsigned short*)(sm + P_H);
            unsigned short* PLs = (unsigned short*)(sm + P_L);
            const int c1a = code[r0], c1b = code[r1];
            #pragma unroll
            for (int half = 0; half < 2; half++) {
                const int e0 = half * 2;
                const int c1 = half ? c1b : c1a;
                const int i1 = half ? i1b : i1a, j1 = half ? j1b : j1a;
                const int row = half ? r1 : r0;
                float mx = -1e30f;
                #pragma unroll
                for (int nt = 0; nt < 8; nt++) {
                    #pragma unroll
                    for (int e = 0; e < 2; e++) {
                        int m = nt * 8 + tig * 2 + e;
                        float t = sacc[nt][e0 + e];
                        if (m < N_) {
                            float bi = __ldg(&bias_table[
                                ((i1 - m / 7 + 6) * 13 + (j1 - m % 7 + 6)) * NH_ + head]);
                            t = (code[m] == c1) ? t + bi : -1e9f;
                        } else t = -1e9f;
                        sacc[nt][e0 + e] = t;
                        mx = fmaxf(mx, t);
                    }
                }
                mx = fmaxf(mx, __shfl_xor_sync(0xffffffffu, mx, 1));
                mx = fmaxf(mx, __shfl_xor_sync(0xffffffffu, mx, 2));
                float sum = 0.0f;
                #pragma unroll
                for (int nt = 0; nt < 8; nt++) {
                    #pragma unroll
                    for (int e = 0; e < 2; e++) {
                        float ex = __expf(sacc[nt][e0 + e] - mx);
                        sacc[nt][e0 + e] = ex;
                        sum += ex;
                    }
                }
                sum += __shfl_xor_sync(0xffffffffu, sum, 1);
                sum += __shfl_xor_sync(0xffffffffu, sum, 2);
                float inv = 1.0f / sum;
                #pragma unroll
                for (int nt = 0; nt < 8; nt++) {
                    uint32_t lo, hi;
                    hi = pack_split2(sacc[nt][e0] * inv, sacc[nt][e0 + 1] * inv, lo);
                    *(uint32_t*)&PHs[row * 72 + nt * 8 + tig * 2] = hi;
                    *(uint32_t*)&PLs[row * 72 + nt * 8 + tig * 2] = lo;
                }
            }
        }
        __syncthreads();

        // ---- O = P @ V (64x32, K=64) ----
        {
            float oacc[4][4] = {};
            #pragma unroll
            for (int ks = 0; ks < 4; ks++) {
                uint32_t ph[4], pl[4];
                LDSM4(ph, pHa + ks * 32);
                LDSM4(pl, pLa + ks * 32);
                #pragma unroll
                for (int p = 0; p < 2; p++) {
                    uint32_t vh[4], vl[4];
                    const uint32_t po = (uint32_t)(ks * 16 * 80 + p * 32);
                    LDSM4T(vh, vH + po);
                    LDSM4T(vl, vL + po);
                    mma_bf16(oacc[2 * p],     ph, vh);
                    mma_bf16(oacc[2 * p],     ph, vl);
                    mma_bf16(oacc[2 * p],     pl, vh);
                    mma_bf16(oacc[2 * p + 1], ph, vh + 2);
                    mma_bf16(oacc[2 * p + 1], ph, vl + 2);
                    mma_bf16(oacc[2 * p + 1], pl, vh + 2);
                }
            }
            __syncthreads();   // Q reads (S-mma) done in all warps before O overlay
            unsigned short* OHs = (unsigned short*)(sm + O_H);
            unsigned short* OLs = (unsigned short*)(sm + O_L);
            #pragma unroll
            for (int nt = 0; nt < 4; nt++) {
                int d0 = nt * 8 + tig * 2;
                uint32_t lo, hi;
                hi = pack_split2(oacc[nt][0], oacc[nt][1], lo);
                *(uint32_t*)&OHs[r0 * 40 + d0] = hi;
                *(uint32_t*)&OLs[r0 * 40 + d0] = lo;
                hi = pack_split2(oacc[nt][2], oacc[nt][3], lo);
                *(uint32_t*)&OHs[r1 * 40 + d0] = hi;
                *(uint32_t*)&OLs[r1 * 40 + d0] = lo;
            }
        }
        __syncthreads();

        // ---- proj accumulation: pacc += O_h @ proj_w[h] (K=32) ----
        #pragma unroll
        for (int ks = 0; ks < 2; ks++) {
            uint32_t oh[4], ol[4];
            LDSM4(oh, oHa + ks * 32);
            LDSM4(ol, oLa + ks * 32);
            #pragma unroll
            for (int p = 0; p < 6; p++) {
                uint32_t wh[4], wl[4];
                const uint32_t bo = (uint32_t)(ks * 16 * 208 + p * 32);
                LDSM4T(wh, bpH + bo);
                LDSM4T(wl, bpL + bo);
                mma_bf16(pacc[2 * p],     oh, wh);
                mma_bf16(pacc[2 * p],     oh, wl);
                mma_bf16(pacc[2 * p],     ol, wh);
                mma_bf16(pacc[2 * p + 1], oh, wh + 2);
                mma_bf16(pacc[2 * p + 1], oh, wl + 2);
                mma_bf16(pacc[2 * p + 1], ol, wh + 2);
            }
        }
    }

    // ---- final: +proj_b, scatter rows < 49 to out (token-natural) ----
    #pragma unroll
    for (int nt = 0; nt < 12; nt++) {
        int col = nt * 8 + tig * 2;
        float2 pb = __ldg((const float2*)&proj_b[col]);
        if (r0 < N_) {
            float2 o; o.x = pacc[nt][0] + pb.x; o.y = pacc[nt][1] + pb.y;
            *(float2*)&out[(size_t)tokv[r0] * 96 + col] = o;
        }
        if (r1 < N_) {
            float2 o; o.x = pacc[nt][2] + pb.x; o.y = pacc[nt][3] + pb.y;
            *(float2*)&out[(size_t)tokv[r1] * 96 + col] = o;
        }
    }
}

// ---------------------------------------------------------------------------
extern "C" void kernel_launch(void* const* d_in, const int* in_sizes, int n_in,
                              void* d_out, int out_size)
{
    (void)in_sizes; (void)n_in; (void)out_size;
    const float* x          = (const float*)d_in[0];
    const float* qkv_w      = (const float*)d_in[1];
    const float* qkv_b      = (const float*)d_in[2];
    const float* proj_w     = (const float*)d_in[3];
    const float* proj_b     = (const float*)d_in[4];
    const float* bias_table = (const float*)d_in[5];
    float* out = (float*)d_out;

    static bool attr_done = false;
    if (!attr_done) {
        cudaFuncSetAttribute(k_fused, cudaFuncAttributeMaxDynamicSharedMemorySize, SMEM_FUSED);
        attr_done = true;
    }

    k_prepack<<<3, 256>>>(qkv_w, proj_w);
    k_fused<<<BNW, 128, SMEM_FUSED>>>(x, qkv_b, proj_b, bias_table, out);
}

// round 15
// speedup vs baseline: 2.0722x; 1.0015x over previous
#include <cuda_runtime.h>
#include <cuda_bf16.h>
#include <cstdint>

// Swin shifted-window MSA: B=32, H=W=112, C=96, ws=7, ss=3, nh=3, hd=32
// Round 14: fused kernel at 256 threads/block (8 warps). Warp = (band, nh):
// band owns 16 M-rows, nh owns half the N-columns of every GEMM phase.
// Softmax via f32 smem S buffer (overlaid on dead BQ region with P).
// Same 111KB smem -> 2 blocks/SM -> 16 warps/SM (occ 12.5% -> 25%).

#define WS_ 7
#define SS_ 3
#define NH_ 3
#define HD_ 32
#define C_  96
#define N_  49
#define HW_ 112
#define BNW 8192

typedef unsigned long long ull;

// prepacked weights (bf16 hi/lo), padded stride 104 ushorts (208B rows)
__device__ __align__(16) unsigned short g_wqkv[3 * 2 * 96 * 104];  // [head][s][96k][104n]
__device__ __align__(16) unsigned short g_wproj[3 * 2 * 32 * 104]; // [head][s][32k][104n]

__device__ __forceinline__ int rcode(int h) {
    return h < (HW_ - WS_) ? 0 : (h < (HW_ - SS_) ? 1 : 2);
}
__device__ __forceinline__ uint32_t smem_u32(const void* p) {
    uint32_t a;
    asm("{ .reg .u64 t; cvta.to.shared.u64 t, %1; cvt.u32.u64 %0, t; }" : "=r"(a) : "l"(p));
    return a;
}
__device__ __forceinline__ void mma_bf16(float* d, const uint32_t* a, const uint32_t* b) {
    asm volatile(
        "mma.sync.aligned.m16n8k16.row.col.f32.bf16.bf16.f32 "
        "{%0,%1,%2,%3}, {%4,%5,%6,%7}, {%8,%9}, {%0,%1,%2,%3};"
        : "+f"(d[0]), "+f"(d[1]), "+f"(d[2]), "+f"(d[3])
        : "r"(a[0]), "r"(a[1]), "r"(a[2]), "r"(a[3]), "r"(b[0]), "r"(b[1]));
}
#define LDSM4(r, addr) \
    asm volatile("ldmatrix.sync.aligned.m8n8.x4.shared.b16 {%0,%1,%2,%3}, [%4];" \
        : "=r"((r)[0]), "=r"((r)[1]), "=r"((r)[2]), "=r"((r)[3]) : "r"(addr))
#define LDSM4T(r, addr) \
    asm volatile("ldmatrix.sync.aligned.m8n8.x4.trans.shared.b16 {%0,%1,%2,%3}, [%4];" \
        : "=r"((r)[0]), "=r"((r)[1]), "=r"((r)[2]), "=r"((r)[3]) : "r"(addr))

__device__ __forceinline__ void split_bf16(float v, unsigned short& h, unsigned short& l) {
    __nv_bfloat16 hb = __float2bfloat16_rn(v);
    __nv_bfloat16 lb = __float2bfloat16_rn(v - __bfloat162float(hb));
    h = __bfloat16_as_ushort(hb);
    l = __bfloat16_as_ushort(lb);
}
__device__ __forceinline__ void split4(float4 v, ull& hh, ull& ll) {
    float vv[4] = {v.x, v.y, v.z, v.w};
    hh = 0; ll = 0;
    #pragma unroll
    for (int e = 0; e < 4; e++) {
        unsigned short h, l;
        split_bf16(vv[e], h, l);
        hh |= (ull)h << (16 * e);
        ll |= (ull)l << (16 * e);
    }
}
__device__ __forceinline__ uint32_t pack_split2(float a, float b, uint32_t& lo) {
    unsigned short h0, l0, h1, l1;
    split_bf16(a, h0, l0);
    split_bf16(b, h1, l1);
    lo = (uint32_t)l0 | ((uint32_t)l1 << 16);
    return (uint32_t)h0 | ((uint32_t)h1 << 16);
}

// ---------------------------------------------------------------------------
// Prepack: qkv_w/proj_w -> bf16 hi/lo per-head tiles. grid=3, block=256.
// ---------------------------------------------------------------------------
__global__ __launch_bounds__(256) void k_prepack(
    const float* __restrict__ qkv_w, const float* __restrict__ proj_w)
{
    const int head = blockIdx.x, tid = threadIdx.x;
    for (int u = tid; u < 96 * 24; u += 256) {
        int k = u / 24, n = (u % 24) * 4;
        int strip = n >> 5, wi = n & 31;
        float4 v = *(const float4*)&qkv_w[k * 288 + strip * 96 + head * 32 + wi];
        ull hh, ll; split4(v, hh, ll);
        *(ull*)&g_wqkv[((head * 2 + 0) * 96 + k) * 104 + n] = hh;
        *(ull*)&g_wqkv[((head * 2 + 1) * 96 + k) * 104 + n] = ll;
    }
    for (int u = tid; u < 32 * 24; u += 256) {
        int k = u / 24, n = (u % 24) * 4;
        float4 v = *(const float4*)&proj_w[(head * 32 + k) * 96 + n];
        ull hh, ll; split4(v, hh, ll);
        *(ull*)&g_wproj[((head * 2 + 0) * 32 + k) * 104 + n] = hh;
        *(ull*)&g_wproj[((head * 2 + 1) * 32 + k) * 104 + n] = ll;
    }
}

// ---------------------------------------------------------------------------
// smem layout (byte offsets)
#define XA_H  0        // A_x hi: 64 x 104 ushorts (208B rows) = 13312
#define XA_L  13312
#define BQ_H  26624    // qkv weights hi: 96 x 208 = 19968 (dead after QKV gemm)
#define BQ_L  46592    // lo: ..66560
#define P_H   26624    // P hi overlays BQ: 64 x 144 = 9216
#define P_L   35840
#define S_O   45056    // S f32 overlays BQ: 64 x 68 x 4 = 17408 -> 62464
#define BP_H  66560    // proj weights hi: 32 x 208 = 6656
#define BP_L  73216
#define Q_H   79872    // 64 x 80 = 5120
#define Q_L   84992
#define O_H   79872    // O overlays Q
#define O_L   84992
#define K_H   90112
#define K_L   95232
#define V_H   100352
#define V_L   105472
#define TOK_O 110592   // int[64]
#define CODE_O 110848  // int[64]
#define SMEM_FUSED 111104
#define S_STR 68

__global__ __launch_bounds__(256) void k_fused(
    const float* __restrict__ x,
    const float* __restrict__ qkv_b,
    const float* __restrict__ proj_b,
    const float* __restrict__ bias_table,
    float* __restrict__ out)
{
    extern __shared__ __align__(16) char sm[];
    const int tid  = threadIdx.x;
    const int wrp  = tid >> 5;
    const int lane = tid & 31;
    const int grp  = lane >> 2;
    const int tig  = lane & 3;
    const int band = wrp & 3;      // 16-row band
    const int nh   = wrp >> 2;     // N-half (0/1)
    const int bw   = blockIdx.x;

    int* tokv = (int*)(sm + TOK_O);
    int* code = (int*)(sm + CODE_O);
    float* S = (float*)(sm + S_O);

    // ---- window token map + region codes + pad zero ----
    {
        int b = bw >> 8, w = bw & 255;
        int wy = w >> 4, wx = w & 15;
        for (int n = tid; n < 64; n += 256) {
            if (n < N_) {
                int i = n / 7, j = n % 7;
                int gy = wy * 7 + i + SS_; if (gy >= HW_) gy -= HW_;
                int gx = wx * 7 + j + SS_; if (gx >= HW_) gx -= HW_;
                tokv[n] = (b * HW_ + gy) * HW_ + gx;
                code[n] = rcode(gy) * 3 + rcode(gx);
            } else { tokv[n] = 0; code[n] = -1; }
        }
        for (int u = tid; u < 15 * 26; u += 256) {
            int r = 49 + u / 26, c = (u % 26) * 4;
            *(ull*)((unsigned short*)(sm + XA_H) + r * 104 + c) = 0;
            *(ull*)((unsigned short*)(sm + XA_L) + r * 104 + c) = 0;
        }
    }
    __syncthreads();

    // ---- gather x window -> A_x bf16 hi/lo ----
    for (int u = tid; u < N_ * 24; u += 256) {
        int n = u / 24, f4 = u % 24;
        float4 v = *(const float4*)&x[(size_t)tokv[n] * 96 + f4 * 4];
        ull hh, ll; split4(v, hh, ll);
        *(ull*)((unsigned short*)(sm + XA_H) + n * 104 + f4 * 4) = hh;
        *(ull*)((unsigned short*)(sm + XA_L) + n * 104 + f4 * 4) = ll;
    }

    // ---- per-lane ldmatrix addresses ----
    const uint32_t sb = smem_u32(sm);
    const uint32_t aoffA = (uint32_t)(band * 16 + (lane & 15)) * 208 + ((lane & 16) ? 16u : 0u);
    const uint32_t axH = sb + XA_H + aoffA, axL = sb + XA_L + aoffA;
    const uint32_t boffB = (uint32_t)(lane & 15) * 208 + ((lane & 16) ? 16u : 0u);
    const uint32_t bqH = sb + BQ_H + boffB + nh * 96, bqL = sb + BQ_L + boffB + nh * 96;
    const uint32_t bpH = sb + BP_H + boffB + nh * 96, bpL = sb + BP_L + boffB + nh * 96;
    const uint32_t toff = (uint32_t)(band * 16 + (lane & 15)) * 80 + ((lane & 16) ? 16u : 0u);
    const uint32_t qH = sb + Q_H + toff, qL = sb + Q_L + toff;
    const uint32_t oHa = sb + O_H + toff, oLa = sb + O_L + toff;
    const uint32_t koff = (uint32_t)((lane & 7) + ((lane & 16) ? 8 : 0)) * 80 + ((lane & 8) ? 16u : 0u);
    const uint32_t kH = sb + K_H + koff, kL = sb + K_L + koff;
    const uint32_t voff = (uint32_t)(lane & 15) * 80 + ((lane & 16) ? 16u : 0u);
    const uint32_t vH = sb + V_H + voff, vL = sb + V_L + voff;
    const uint32_t poff = (uint32_t)(band * 16 + (lane & 15)) * 144 + ((lane & 16) ? 16u : 0u);
    const uint32_t pHa = sb + P_H + poff, pLa = sb + P_L + poff;

    const int r0 = band * 16 + grp, r1 = r0 + 8;

    float pacc[6][4] = {};   // proj accumulator (this warp's N-half), kept across heads

    for (int head = 0; head < 3; head++) {
        __syncthreads();  // prev head's P/S/BP reads done before refill
        // ---- weight fills (256 threads, straight 16B copies) ----
        {
            const uint4* sq = (const uint4*)(g_wqkv + head * 2 * 96 * 104);
            uint4* dqH = (uint4*)(sm + BQ_H);
            uint4* dqL = (uint4*)(sm + BQ_L);
            for (int u = tid; u < 1248; u += 256) { dqH[u] = sq[u]; dqL[u] = sq[1248 + u]; }
            const uint4* sp = (const uint4*)(g_wproj + head * 2 * 32 * 104);
            uint4* dpH = (uint4*)(sm + BP_H);
            uint4* dpL = (uint4*)(sm + BP_L);
            for (int u = tid; u < 416; u += 256) { dpH[u] = sp[u]; dpL[u] = sp[416 + u]; }
        }
        __syncthreads();

        // ---- QKV GEMM: warp does [16 x 48] of [64x96]@[96x96] ----
        {
            float acc[6][4] = {};
            #pragma unroll
            for (int ks = 0; ks < 6; ks++) {
                uint32_t ah[4], al[4];
                LDSM4(ah, axH + ks * 32);
                LDSM4(al, axL + ks * 32);
                #pragma unroll
                for (int pl = 0; pl < 3; pl++) {
                    uint32_t bh[4], bl[4];
                    const uint32_t bo = (uint32_t)(ks * 16 * 208 + pl * 32);
                    LDSM4T(bh, bqH + bo);
                    LDSM4T(bl, bqL + bo);
                    mma_bf16(acc[2 * pl],     ah, bh);
                    mma_bf16(acc[2 * pl],     ah, bl);
                    mma_bf16(acc[2 * pl],     al, bh);
                    mma_bf16(acc[2 * pl + 1], ah, bh + 2);
                    mma_bf16(acc[2 * pl + 1], ah, bl + 2);
                    mma_bf16(acc[2 * pl + 1], al, bh + 2);
                }
            }
            // epilogue: +bias (q scaled), split bf16 -> Q/K/V tiles
            #pragma unroll
            for (int ntl = 0; ntl < 6; ntl++) {
                int col = nh * 48 + ntl * 8 + tig * 2;   // 0..95 within q|k|v layout
                int strip = col >> 5, lc = col & 31;
                int gcol = strip * 96 + head * 32 + lc;
                float2 bv = __ldg((const float2*)&qkv_b[gcol]);
                float sc = (strip == 0) ? 0.17677669529663687f : 1.0f;
                int tb_h = (strip == 0) ? Q_H : (strip == 1) ? K_H : V_H;
                int tb_l = (strip == 0) ? Q_L : (strip == 1) ? K_L : V_L;
                unsigned short* TH = (unsigned short*)(sm + tb_h);
                unsigned short* TL = (unsigned short*)(sm + tb_l);
                uint32_t lo, hi;
                hi = pack_split2((acc[ntl][0] + bv.x) * sc, (acc[ntl][1] + bv.y) * sc, lo);
                *(uint32_t*)&TH[r0 * 40 + lc] = hi;
                *(uint32_t*)&TL[r0 * 40 + lc] = lo;
                hi = pack_split2((acc[ntl][2] + bv.x) * sc, (acc[ntl][3] + bv.y) * sc, lo);
                *(uint32_t*)&TH[r1 * 40 + lc] = hi;
                *(uint32_t*)&TL[r1 * 40 + lc] = lo;
            }
        }
        __syncthreads();

        // ---- S = q @ k^T: warp does [16 x 32] of [64x64], K=32 ----
        {
            float sacc[4][4] = {};
            #pragma unroll
            for (int ks = 0; ks < 2; ks++) {
                uint32_t ah[4], al[4];
                LDSM4(ah, qH + ks * 32);
                LDSM4(al, qL + ks * 32);
                #pragma unroll
                for (int pl = 0; pl < 2; pl++) {
                    uint32_t kh[4], kl[4];
                    const uint32_t po = (uint32_t)((nh * 2 + pl) * 16 * 80 + ks * 32);
                    LDSM4(kh, kH + po);
                    LDSM4(kl, kL + po);
                    mma_bf16(sacc[2 * pl],     ah, kh);
                    mma_bf16(sacc[2 * pl],     ah, kl);
                    mma_bf16(sacc[2 * pl],     al, kh);
                    mma_bf16(sacc[2 * pl + 1], ah, kh + 2);
                    mma_bf16(sacc[2 * pl + 1], ah, kl + 2);
                    mma_bf16(sacc[2 * pl + 1], al, kh + 2);
                }
            }
            #pragma unroll
            for (int t = 0; t < 4; t++) {
                int col = (nh * 2 + (t >> 1)) * 16 + (t & 1) * 8 + tig * 2;
                S[r0 * S_STR + col] = sacc[t][0]; S[r0 * S_STR + col + 1] = sacc[t][1];
                S[r1 * S_STR + col] = sacc[t][2]; S[r1 * S_STR + col + 1] = sacc[t][3];
            }
        }
        __syncthreads();

        // ---- softmax: thread owns row=tid>>2, 16 cols; reduce over 4 lanes ----
        {
            unsigned short* PHs = (unsigned short*)(sm + P_H);
            unsigned short* PLs = (unsigned short*)(sm + P_L);
            const int row = tid >> 2;
            const int c4 = (tid & 3) * 16;
            const bool rowok = row < N_;
            const int c1 = code[row];
            const int i1 = row / 7, j1 = row % 7;
            float vals[16];
            float mx = -1e30f;
            #pragma unroll
            for (int c = 0; c < 16; c++) {
                int m = c4 + c;
                float t = -1e9f;
                if (rowok && m < N_ && code[m] == c1) {
                    float bi = __ldg(&bias_table[
                        ((i1 - m / 7 + 6) * 13 + (j1 - m % 7 + 6)) * NH_ + head]);
                    t = S[row * S_STR + m] + bi;
                }
                vals[c] = t;
                mx = fmaxf(mx, t);
            }
            mx = fmaxf(mx, __shfl_xor_sync(0xffffffffu, mx, 1));
            mx = fmaxf(mx, __shfl_xor_sync(0xffffffffu, mx, 2));
            float sum = 0.0f;
            #pragma unroll
            for (int c = 0; c < 16; c++) {
                float ex = __expf(vals[c] - mx);
                vals[c] = ex;
                sum += ex;
            }
            sum += __shfl_xor_sync(0xffffffffu, sum, 1);
            sum += __shfl_xor_sync(0xffffffffu, sum, 2);
            float inv = 1.0f / sum;
            #pragma unroll
            for (int i = 0; i < 8; i++) {
                uint32_t lo, hi;
                hi = pack_split2(vals[2 * i] * inv, vals[2 * i + 1] * inv, lo);
                *(uint32_t*)&PHs[row * 72 + c4 + 2 * i] = hi;
                *(uint32_t*)&PLs[row * 72 + c4 + 2 * i] = lo;
            }
        }
        __syncthreads();

        // ---- O = P @ V: warp does [16 x 16] of [64x32], K=64 ----
        {
            float oacc[2][4] = {};
            #pragma unroll
            for (int ks = 0; ks < 4; ks++) {
                uint32_t ph[4], pl[4];
                LDSM4(ph, pHa + ks * 32);
                LDSM4(pl, pLa + ks * 32);
                uint32_t vh[4], vl[4];
                const uint32_t po = (uint32_t)(ks * 16 * 80 + nh * 32);
                LDSM4T(vh, vH + po);
                LDSM4T(vl, vL + po);
                mma_bf16(oacc[0], ph, vh);
                mma_bf16(oacc[0], ph, vl);
                mma_bf16(oacc[0], pl, vh);
                mma_bf16(oacc[1], ph, vh + 2);
                mma_bf16(oacc[1], ph, vl + 2);
                mma_bf16(oacc[1], pl, vh + 2);
            }
            unsigned short* OHs = (unsigned short*)(sm + O_H);
            unsigned short* OLs = (unsigned short*)(sm + O_L);
            #pragma unroll
            for (int sub = 0; sub < 2; sub++) {
                int d0 = nh * 16 + sub * 8 + tig * 2;
                uint32_t lo, hi;
                hi = pack_split2(oacc[sub][0], oacc[sub][1], lo);
                *(uint32_t*)&OHs[r0 * 40 + d0] = hi;
                *(uint32_t*)&OLs[r0 * 40 + d0] = lo;
                hi = pack_split2(oacc[sub][2], oacc[sub][3], lo);
                *(uint32_t*)&OHs[r1 * 40 + d0] = hi;
                *(uint32_t*)&OLs[r1 * 40 + d0] = lo;
            }
        }
        __syncthreads();

        // ---- proj accumulation: pacc += O_h @ proj_w[h] (K=32) ----
        #pragma unroll
        for (int ks = 0; ks < 2; ks++) {
            uint32_t oh[4], ol[4];
            LDSM4(oh, oHa + ks * 32);
            LDSM4(ol, oLa + ks * 32);
            #pragma unroll
            for (int pl = 0; pl < 3; pl++) {
                uint32_t wh[4], wl[4];
                const uint32_t bo = (uint32_t)(ks * 16 * 208 + pl * 32);
                LDSM4T(wh, bpH + bo);
                LDSM4T(wl, bpL + bo);
                mma_bf16(pacc[2 * pl],     oh, wh);
                mma_bf16(pacc[2 * pl],     oh, wl);
                mma_bf16(pacc[2 * pl],     ol, wh);
                mma_bf16(pacc[2 * pl + 1], oh, wh + 2);
                mma_bf16(pacc[2 * pl + 1], oh, wl + 2);
                mma_bf16(pacc[2 * pl + 1], ol, wh + 2);
            }
        }
    }

    // ---- final: +proj_b, scatter rows < 49 (token-natural) ----
    #pragma unroll
    for (int ntl = 0; ntl < 6; ntl++) {
        int col = nh * 48 + ntl * 8 + tig * 2;
        float2 pb = __ldg((const float2*)&proj_b[col]);
        if (r0 < N_) {
            float2 o; o.x = pacc[ntl][0] + pb.x; o.y = pacc[ntl][1] + pb.y;
            *(float2*)&out[(size_t)tokv[r0] * 96 + col] = o;
        }
        if (r1 < N_) {
            float2 o; o.x = pacc[ntl][2] + pb.x; o.y = pacc[ntl][3] + pb.y;
            *(float2*)&out[(size_t)tokv[r1] * 96 + col] = o;
        }
    }
}

// ---------------------------------------------------------------------------
extern "C" void kernel_launch(void* const* d_in, const int* in_sizes, int n_in,
                              void* d_out, int out_size)
{
    (void)in_sizes; (void)n_in; (void)out_size;
    const float* x          = (const float*)d_in[0];
    const float* qkv_w      = (const float*)d_in[1];
    const float* qkv_b      = (const float*)d_in[2];
    const float* proj_w     = (const float*)d_in[3];
    const float* proj_b     = (const float*)d_in[4];
    const float* bias_table = (const float*)d_in[5];
    float* out = (float*)d_out;

    static bool attr_done = false;
    if (!attr_done) {
        cudaFuncSetAttribute(k_fused, cudaFuncAttributeMaxDynamicSharedMemorySize, SMEM_FUSED);
        attr_done = true;
    }

    k_prepack<<<3, 256>>>(qkv_w, proj_w);
    k_fused<<<BNW, 256, SMEM_FUSED>>>(x, qkv_b, proj_b, bias_table, out);
}

// round 16
// speedup vs baseline: 2.0946x; 1.0108x over previous
#include <cuda_runtime.h>
#include <cuda_fp16.h>
#include <cstdint>

// Swin shifted-window MSA: B=32, H=W=112, C=96, ws=7, ss=3, nh=3, hd=32
// Round 15: precision-for-throughput trade. fp16 scheme:
//   - x split hi/lo fp16; weights SINGLE fp16 -> QKV gemm 2-term
//   - Q/K/V/P/O single fp16; S / PV / proj gemms 1-term
// mma count/block 4608 -> 2400, LDSM ~halved, weight fills halved.
// A-fragments register-cached across heads; S overlays XA -> 67.5KB smem
// -> 3 blocks/SM (occ 37.5%).

#define WS_ 7
#define SS_ 3
#define NH_ 3
#define HD_ 32
#define C_  96
#define N_  49
#define HW_ 112
#define BNW 8192

typedef unsigned long long ull;

// prepacked single-fp16 weights, padded stride 104 ushorts (208B rows)
__device__ __align__(16) unsigned short g_wqkv[3 * 96 * 104];  // [head][96k][104n]
__device__ __align__(16) unsigned short g_wproj[3 * 32 * 104]; // [head][32k][104n]

__device__ __forceinline__ int rcode(int h) {
    return h < (HW_ - WS_) ? 0 : (h < (HW_ - SS_) ? 1 : 2);
}
__device__ __forceinline__ uint32_t smem_u32(const void* p) {
    uint32_t a;
    asm("{ .reg .u64 t; cvta.to.shared.u64 t, %1; cvt.u32.u64 %0, t; }" : "=r"(a) : "l"(p));
    return a;
}
// HMMA m16n8k16 row.col f32 += f16*f16
__device__ __forceinline__ void mma_f16(float* d, const uint32_t* a, const uint32_t* b) {
    asm volatile(
        "mma.sync.aligned.m16n8k16.row.col.f32.f16.f16.f32 "
        "{%0,%1,%2,%3}, {%4,%5,%6,%7}, {%8,%9}, {%0,%1,%2,%3};"
        : "+f"(d[0]), "+f"(d[1]), "+f"(d[2]), "+f"(d[3])
        : "r"(a[0]), "r"(a[1]), "r"(a[2]), "r"(a[3]), "r"(b[0]), "r"(b[1]));
}
#define LDSM4(r, addr) \
    asm volatile("ldmatrix.sync.aligned.m8n8.x4.shared.b16 {%0,%1,%2,%3}, [%4];" \
        : "=r"((r)[0]), "=r"((r)[1]), "=r"((r)[2]), "=r"((r)[3]) : "r"(addr))
#define LDSM4T(r, addr) \
    asm volatile("ldmatrix.sync.aligned.m8n8.x4.trans.shared.b16 {%0,%1,%2,%3}, [%4];" \
        : "=r"((r)[0]), "=r"((r)[1]), "=r"((r)[2]), "=r"((r)[3]) : "r"(addr))

__device__ __forceinline__ uint32_t pack_f16x2(float a, float b) {
    __half2 h = __floats2half2_rn(a, b);   // a -> low half
    return *(uint32_t*)&h;
}
__device__ __forceinline__ ull cvt4_f16(float4 v) {
    uint32_t lo = pack_f16x2(v.x, v.y), hi = pack_f16x2(v.z, v.w);
    return (ull)lo | ((ull)hi << 32);
}
__device__ __forceinline__ void split4_f16(float4 v, ull& hh, ull& ll) {
    float vv[4] = {v.x, v.y, v.z, v.w};
    hh = 0; ll = 0;
    #pragma unroll
    for (int e = 0; e < 4; e++) {
        __half h = __float2half_rn(vv[e]);
        __half l = __float2half_rn(vv[e] - __half2float(h));
        hh |= (ull)__half_as_ushort(h) << (16 * e);
        ll |= (ull)__half_as_ushort(l) << (16 * e);
    }
}

// ---------------------------------------------------------------------------
// Prepack: weights -> single fp16 per-head tiles. grid=3, block=256.
// qkv tile n-layout: n<32:q(head), 32..63:k(head), 64..95:v(head)
// ---------------------------------------------------------------------------
__global__ __launch_bounds__(256) void k_prepack(
    const float* __restrict__ qkv_w, const float* __restrict__ proj_w)
{
    const int head = blockIdx.x, tid = threadIdx.x;
    for (int u = tid; u < 96 * 24; u += 256) {
        int k = u / 24, n = (u % 24) * 4;
        int strip = n >> 5, wi = n & 31;
        float4 v = *(const float4*)&qkv_w[k * 288 + strip * 96 + head * 32 + wi];
        *(ull*)&g_wqkv[(head * 96 + k) * 104 + n] = cvt4_f16(v);
    }
    for (int u = tid; u < 32 * 24; u += 256) {
        int k = u / 24, n = (u % 24) * 4;
        float4 v = *(const float4*)&proj_w[(head * 32 + k) * 96 + n];
        *(ull*)&g_wproj[(head * 32 + k) * 104 + n] = cvt4_f16(v);
    }
}

// ---------------------------------------------------------------------------
// smem layout (byte offsets)
#define XA_H  0        // x hi fp16: 64 x 104 us (208B rows) = 13312
#define XA_L  13312    // -> 26624 ; S (f32 64x68 = 17408) overlays XA after A-cache
#define S_O   0
#define BQ_O  26624    // qkv weights single: 96 x 208 = 19968 -> 46592
#define P_O   26624    // P single overlays BQ: 64 x 144 = 9216
#define BP_O  46592    // proj weights single: 32 x 208 = 6656 -> 53248
#define Q_O   53248    // 64 x 80 = 5120
#define O_O   53248    // O overlays Q
#define K_O   58368
#define V_O   63488
#define TOK_O 68608    // int[64]
#define CODE_O 68864   // int[64]
#define SMEM_FUSED 69120
#define S_STR 68

__global__ __launch_bounds__(256, 3) void k_fused(
    const float* __restrict__ x,
    const float* __restrict__ qkv_b,
    const float* __restrict__ proj_b,
    const float* __restrict__ bias_table,
    float* __restrict__ out)
{
    extern __shared__ __align__(16) char sm[];
    const int tid  = threadIdx.x;
    const int wrp  = tid >> 5;
    const int lane = tid & 31;
    const int grp  = lane >> 2;
    const int tig  = lane & 3;
    const int band = wrp & 3;      // 16-row band
    const int nh   = wrp >> 2;     // N-half (0/1)
    const int bw   = blockIdx.x;

    int* tokv = (int*)(sm + TOK_O);
    int* code = (int*)(sm + CODE_O);
    float* S = (float*)(sm + S_O);

    // ---- window token map + region codes + pad zero ----
    {
        int b = bw >> 8, w = bw & 255;
        int wy = w >> 4, wx = w & 15;
        for (int n = tid; n < 64; n += 256) {
            if (n < N_) {
                int i = n / 7, j = n % 7;
                int gy = wy * 7 + i + SS_; if (gy >= HW_) gy -= HW_;
                int gx = wx * 7 + j + SS_; if (gx >= HW_) gx -= HW_;
                tokv[n] = (b * HW_ + gy) * HW_ + gx;
                code[n] = rcode(gy) * 3 + rcode(gx);
            } else { tokv[n] = 0; code[n] = -1; }
        }
        for (int u = tid; u < 15 * 26; u += 256) {
            int r = 49 + u / 26, c = (u % 26) * 4;
            *(ull*)((unsigned short*)(sm + XA_H) + r * 104 + c) = 0;
            *(ull*)((unsigned short*)(sm + XA_L) + r * 104 + c) = 0;
        }
    }
    __syncthreads();

    // ---- gather x window -> hi/lo fp16 ----
    for (int u = tid; u < N_ * 24; u += 256) {
        int n = u / 24, f4 = u % 24;
        float4 v = *(const float4*)&x[(size_t)tokv[n] * 96 + f4 * 4];
        ull hh, ll; split4_f16(v, hh, ll);
        *(ull*)((unsigned short*)(sm + XA_H) + n * 104 + f4 * 4) = hh;
        *(ull*)((unsigned short*)(sm + XA_L) + n * 104 + f4 * 4) = ll;
    }

    // ---- per-lane ldmatrix addresses ----
    const uint32_t sb = smem_u32(sm);
    const uint32_t aoffA = (uint32_t)(band * 16 + (lane & 15)) * 208 + ((lane & 16) ? 16u : 0u);
    const uint32_t boffB = (uint32_t)(lane & 15) * 208 + ((lane & 16) ? 16u : 0u);
    const uint32_t bq = sb + BQ_O + boffB + nh * 96;
    const uint32_t bp = sb + BP_O + boffB + nh * 96;
    const uint32_t toff = (uint32_t)(band * 16 + (lane & 15)) * 80 + ((lane & 16) ? 16u : 0u);
    const uint32_t qA = sb + Q_O + toff;
    const uint32_t oA = sb + O_O + toff;
    const uint32_t koff = (uint32_t)((lane & 7) + ((lane & 16) ? 8 : 0)) * 80 + ((lane & 8) ? 16u : 0u);
    const uint32_t kA = sb + K_O + koff;
    const uint32_t voff = (uint32_t)(lane & 15) * 80 + ((lane & 16) ? 16u : 0u);
    const uint32_t vA = sb + V_O + voff;
    const uint32_t poff = (uint32_t)(band * 16 + (lane & 15)) * 144 + ((lane & 16) ? 16u : 0u);
    const uint32_t pA = sb + P_O + poff;

    const int r0 = band * 16 + grp, r1 = r0 + 8;

    __syncthreads();

    // ---- cache A fragments (hi/lo) in registers across all heads ----
    uint32_t axh[6][4], axl[6][4];
    #pragma unroll
    for (int ks = 0; ks < 6; ks++) {
        LDSM4(axh[ks], sb + XA_H + aoffA + ks * 32);
        LDSM4(axl[ks], sb + XA_L + aoffA + ks * 32);
    }

    float pacc[6][4] = {};   // proj accumulator (this warp's N-half)

    for (int head = 0; head < 3; head++) {
        __syncthreads();  // prev head's P/S/BP reads done; A-cache done (head 0)
        // ---- weight fills (straight 16B copies) ----
        {
            const uint4* sq = (const uint4*)(g_wqkv + head * 96 * 104);
            uint4* dq = (uint4*)(sm + BQ_O);
            for (int u = tid; u < 1248; u += 256) dq[u] = sq[u];
            const uint4* sp = (const uint4*)(g_wproj + head * 32 * 104);
            uint4* dp = (uint4*)(sm + BP_O);
            for (int u = tid; u < 416; u += 256) dp[u] = sp[u];
        }
        __syncthreads();

        // ---- QKV GEMM (2-term): warp does [16 x 48] of [64x96]@[96x96] ----
        {
            float acc[6][4] = {};
            #pragma unroll
            for (int ks = 0; ks < 6; ks++) {
                #pragma unroll
                for (int pl = 0; pl < 3; pl++) {
                    uint32_t bf[4];
                    LDSM4T(bf, bq + (uint32_t)(ks * 16 * 208 + pl * 32));
                    mma_f16(acc[2 * pl],     axh[ks], bf);
                    mma_f16(acc[2 * pl],     axl[ks], bf);
                    mma_f16(acc[2 * pl + 1], axh[ks], bf + 2);
                    mma_f16(acc[2 * pl + 1], axl[ks], bf + 2);
                }
            }
            // epilogue: +bias (q scaled), to single-fp16 Q/K/V tiles
            #pragma unroll
            for (int ntl = 0; ntl < 6; ntl++) {
                int col = nh * 48 + ntl * 8 + tig * 2;   // 0..95 in q|k|v layout
                int strip = col >> 5, lc = col & 31;
                int gcol = strip * 96 + head * 32 + lc;
                float2 bv = __ldg((const float2*)&qkv_b[gcol]);
                float sc = (strip == 0) ? 0.17677669529663687f : 1.0f;
                int tb = (strip == 0) ? Q_O : (strip == 1) ? K_O : V_O;
                unsigned short* T = (unsigned short*)(sm + tb);
                *(uint32_t*)&T[r0 * 40 + lc] =
                    pack_f16x2((acc[ntl][0] + bv.x) * sc, (acc[ntl][1] + bv.y) * sc);
                *(uint32_t*)&T[r1 * 40 + lc] =
                    pack_f16x2((acc[ntl][2] + bv.x) * sc, (acc[ntl][3] + bv.y) * sc);
            }
        }
        __syncthreads();

        // ---- S = q @ k^T (1-term): warp does [16 x 32] of [64x64], K=32 ----
        {
            float sacc[4][4] = {};
            #pragma unroll
            for (int ks = 0; ks < 2; ks++) {
                uint32_t qf[4];
                LDSM4(qf, qA + ks * 32);
                #pragma unroll
                for (int pl = 0; pl < 2; pl++) {
                    uint32_t kf[4];
                    LDSM4(kf, kA + (uint32_t)((nh * 2 + pl) * 16 * 80 + ks * 32));
                    mma_f16(sacc[2 * pl],     qf, kf);
                    mma_f16(sacc[2 * pl + 1], qf, kf + 2);
                }
            }
            #pragma unroll
            for (int t = 0; t < 4; t++) {
                int col = (nh * 2 + (t >> 1)) * 16 + (t & 1) * 8 + tig * 2;
                S[r0 * S_STR + col] = sacc[t][0]; S[r0 * S_STR + col + 1] = sacc[t][1];
                S[r1 * S_STR + col] = sacc[t][2]; S[r1 * S_STR + col + 1] = sacc[t][3];
            }
        }
        __syncthreads();

        // ---- softmax: thread owns row=tid>>2, 16 cols; reduce over 4 lanes ----
        {
            unsigned short* P = (unsigned short*)(sm + P_O);
            const int row = tid >> 2;
            const int c4 = (tid & 3) * 16;
            const bool rowok = row < N_;
            const int c1 = code[row];
            const int i1 = row / 7, j1 = row % 7;
            float vals[16];
            float mx = -1e30f;
            #pragma unroll
            for (int c = 0; c < 16; c++) {
                int m = c4 + c;
                float t = -1e9f;
                if (rowok && m < N_ && code[m] == c1) {
                    float bi = __ldg(&bias_table[
                        ((i1 - m / 7 + 6) * 13 + (j1 - m % 7 + 6)) * NH_ + head]);
                    t = S[row * S_STR + m] + bi;
                }
                vals[c] = t;
                mx = fmaxf(mx, t);
            }
            mx = fmaxf(mx, __shfl_xor_sync(0xffffffffu, mx, 1));
            mx = fmaxf(mx, __shfl_xor_sync(0xffffffffu, mx, 2));
            float sum = 0.0f;
            #pragma unroll
            for (int c = 0; c < 16; c++) {
                float ex = __expf(vals[c] - mx);
                vals[c] = ex;
                sum += ex;
            }
            sum += __shfl_xor_sync(0xffffffffu, sum, 1);
            sum += __shfl_xor_sync(0xffffffffu, sum, 2);
            float inv = 1.0f / sum;
            #pragma unroll
            for (int i = 0; i < 8; i++) {
                *(uint32_t*)&P[row * 72 + c4 + 2 * i] =
                    pack_f16x2(vals[2 * i] * inv, vals[2 * i + 1] * inv);
            }
        }
        __syncthreads();

        // ---- O = P @ V (1-term): warp does [16 x 16] of [64x32], K=64 ----
        {
            float oacc[2][4] = {};
            #pragma unroll
            for (int ks = 0; ks < 4; ks++) {
                uint32_t pf[4], vf[4];
                LDSM4(pf, pA + ks * 32);
                LDSM4T(vf, vA + (uint32_t)(ks * 16 * 80 + nh * 32));
                mma_f16(oacc[0], pf, vf);
                mma_f16(oacc[1], pf, vf + 2);
            }
            unsigned short* O = (unsigned short*)(sm + O_O);
            #pragma unroll
            for (int sub = 0; sub < 2; sub++) {
                int d0 = nh * 16 + sub * 8 + tig * 2;
                *(uint32_t*)&O[r0 * 40 + d0] = pack_f16x2(oacc[sub][0], oacc[sub][1]);
                *(uint32_t*)&O[r1 * 40 + d0] = pack_f16x2(oacc[sub][2], oacc[sub][3]);
            }
        }
        __syncthreads();

        // ---- proj accumulation (1-term): pacc += O_h @ proj_w[h] (K=32) ----
        #pragma unroll
        for (int ks = 0; ks < 2; ks++) {
            uint32_t of[4];
            LDSM4(of, oA + ks * 32);
            #pragma unroll
            for (int pl = 0; pl < 3; pl++) {
                uint32_t wf[4];
                LDSM4T(wf, bp + (uint32_t)(ks * 16 * 208 + pl * 32));
                mma_f16(pacc[2 * pl],     of, wf);
                mma_f16(pacc[2 * pl + 1], of, wf + 2);
            }
        }
    }

    // ---- final: +proj_b, scatter rows < 49 (token-natural) ----
    #pragma unroll
    for (int ntl = 0; ntl < 6; ntl++) {
        int col = nh * 48 + ntl * 8 + tig * 2;
        float2 pb = __ldg((const float2*)&proj_b[col]);
        if (r0 < N_) {
            float2 o; o.x = pacc[ntl][0] + pb.x; o.y = pacc[ntl][1] + pb.y;
            *(float2*)&out[(size_t)tokv[r0] * 96 + col] = o;
        }
        if (r1 < N_) {
            float2 o; o.x = pacc[ntl][2] + pb.x; o.y = pacc[ntl][3] + pb.y;
            *(float2*)&out[(size_t)tokv[r1] * 96 + col] = o;
        }
    }
}

// ---------------------------------------------------------------------------
extern "C" void kernel_launch(void* const* d_in, const int* in_sizes, int n_in,
                              void* d_out, int out_size)
{
    (void)in_sizes; (void)n_in; (void)out_size;
    const float* x          = (const float*)d_in[0];
    const float* qkv_w      = (const float*)d_in[1];
    const float* qkv_b      = (const float*)d_in[2];
    const float* proj_w     = (const float*)d_in[3];
    const float* proj_b     = (const float*)d_in[4];
    const float* bias_table = (const float*)d_in[5];
    float* out = (float*)d_out;

    static bool attr_done = false;
    if (!attr_done) {
        cudaFuncSetAttribute(k_fused, cudaFuncAttributeMaxDynamicSharedMemorySize, SMEM_FUSED);
        attr_done = true;
    }

    k_prepack<<<3, 256>>>(qkv_w, proj_w);
    k_fused<<<BNW, 256, SMEM_FUSED>>>(x, qkv_b, proj_b, bias_table, out);
}

// round 17
// speedup vs baseline: 3.7867x; 1.8078x over previous
#include <cuda_runtime.h>
#include <cuda_fp16.h>
#include <cstdint>

// Swin shifted-window MSA: B=32, H=W=112, C=96, ws=7, ss=3, nh=3, hd=32
// Round 16: de-serialize the fused kernel. All 3 heads processed at once:
//   phase 1: gather x + fill Wqkv(all heads)           | bar
//   phase 2: QKV [64x288] gemm -> Q|K|V tiles          | bar
//   phase 3: S + register softmax (12 tiles) + Wproj fill -> P | bar
//   phase 4: PV (12 tiles) -> O (overlays XA)          | bar
//   phase 5: proj [64x96] K=96 + scatter out
// 4 barriers/block (was 18). fp16 1-term everywhere (x single fp16).
// smem 108KB -> 2 blocks/SM.

#define WS_ 7
#define SS_ 3
#define NH_ 3
#define HD_ 32
#define C_  96
#define N_  49
#define HW_ 112
#define BNW 8192

typedef unsigned long long ull;

// prepacked single-fp16 weights
__device__ __align__(16) unsigned short g_wqkv[96 * 296];  // [96k][288n +8 pad]
__device__ __align__(16) unsigned short g_wproj[96 * 104]; // [96k][96n +8 pad]

__device__ __forceinline__ int rcode(int h) {
    return h < (HW_ - WS_) ? 0 : (h < (HW_ - SS_) ? 1 : 2);
}
__device__ __forceinline__ uint32_t smem_u32(const void* p) {
    uint32_t a;
    asm("{ .reg .u64 t; cvta.to.shared.u64 t, %1; cvt.u32.u64 %0, t; }" : "=r"(a) : "l"(p));
    return a;
}
__device__ __forceinline__ void mma_f16(float* d, const uint32_t* a, const uint32_t* b) {
    asm volatile(
        "mma.sync.aligned.m16n8k16.row.col.f32.f16.f16.f32 "
        "{%0,%1,%2,%3}, {%4,%5,%6,%7}, {%8,%9}, {%0,%1,%2,%3};"
        : "+f"(d[0]), "+f"(d[1]), "+f"(d[2]), "+f"(d[3])
        : "r"(a[0]), "r"(a[1]), "r"(a[2]), "r"(a[3]), "r"(b[0]), "r"(b[1]));
}
#define LDSM4(r, addr) \
    asm volatile("ldmatrix.sync.aligned.m8n8.x4.shared.b16 {%0,%1,%2,%3}, [%4];" \
        : "=r"((r)[0]), "=r"((r)[1]), "=r"((r)[2]), "=r"((r)[3]) : "r"(addr))
#define LDSM4T(r, addr) \
    asm volatile("ldmatrix.sync.aligned.m8n8.x4.trans.shared.b16 {%0,%1,%2,%3}, [%4];" \
        : "=r"((r)[0]), "=r"((r)[1]), "=r"((r)[2]), "=r"((r)[3]) : "r"(addr))

__device__ __forceinline__ uint32_t pack_f16x2(float a, float b) {
    __half2 h = __floats2half2_rn(a, b);
    return *(uint32_t*)&h;
}
__device__ __forceinline__ ull cvt4_f16(float4 v) {
    uint32_t lo = pack_f16x2(v.x, v.y), hi = pack_f16x2(v.z, v.w);
    return (ull)lo | ((ull)hi << 32);
}

// ---------------------------------------------------------------------------
__global__ __launch_bounds__(256) void k_prepack(
    const float* __restrict__ qkv_w, const float* __restrict__ proj_w)
{
    const int tid = threadIdx.x;
    for (int u = tid; u < 96 * 72; u += 256) {
        int k = u / 72, n4 = u % 72;
        float4 v = *(const float4*)&qkv_w[k * 288 + n4 * 4];
        *(ull*)&g_wqkv[k * 296 + n4 * 4] = cvt4_f16(v);
    }
    for (int u = tid; u < 96 * 24; u += 256) {
        int k = u / 24, n4 = u % 24;
        float4 v = *(const float4*)&proj_w[k * 96 + n4 * 4];
        *(ull*)&g_wproj[k * 104 + n4 * 4] = cvt4_f16(v);
    }
}

// ---------------------------------------------------------------------------
// smem layout (byte offsets)
#define XA_O  0        // x fp16 [64][104] stride 208B = 13312 ; O overlays
#define O_O   0
#define WQ_O  13312    // Wqkv fp16 [96][296] stride 592B = 56832
#define P_O   13312    // P overlays WQ: 3 x [64][72us] (144B) = 27648
#define WP_O  41728    // Wproj overlays WQ tail: [96][104] = 19968 -> 61696
#define Q_O   70144    // [64][104] = 13312 (cols head*32+d)
#define K_O   83456
#define V_O   96768
#define TOK_O 110080
#define CODE_O 110336
#define SMEM_FUSED 110592

__global__ __launch_bounds__(256, 2) void k_fused(
    const float* __restrict__ x,
    const float* __restrict__ qkv_b,
    const float* __restrict__ proj_b,
    const float* __restrict__ bias_table,
    float* __restrict__ out)
{
    extern __shared__ __align__(16) char sm[];
    const int tid  = threadIdx.x;
    const int wrp  = tid >> 5;
    const int lane = tid & 31;
    const int grp  = lane >> 2;
    const int tig  = lane & 3;
    const int band = wrp & 3;      // 16-row band (QKV / proj phases)
    const int nh   = wrp >> 2;     // N-half (QKV / proj phases)
    const int bw   = blockIdx.x;

    int* tokv = (int*)(sm + TOK_O);
    int* code = (int*)(sm + CODE_O);

    const int b = bw >> 8, w = bw & 255;
    const int wy = w >> 4, wx = w & 15;

    // ---- phase 1: tok/code, pad zero, gather x, fill Wqkv ----
    for (int n = tid; n < 64; n += 256) {
        if (n < N_) {
            int i = n / 7, j = n % 7;
            int gy = wy * 7 + i + SS_; if (gy >= HW_) gy -= HW_;
            int gx = wx * 7 + j + SS_; if (gx >= HW_) gx -= HW_;
            tokv[n] = (b * HW_ + gy) * HW_ + gx;
            code[n] = rcode(gy) * 3 + rcode(gx);
        } else { tokv[n] = 0; code[n] = -1; }
    }
    for (int u = tid; u < 15 * 26; u += 256) {
        int r = 49 + u / 26, c = (u % 26) * 4;
        *(ull*)((unsigned short*)(sm + XA_O) + r * 104 + c) = 0;
    }
    for (int u = tid; u < N_ * 24; u += 256) {
        int n = u / 24, f4 = u % 24;
        int i = n / 7, j = n % 7;
        int gy = wy * 7 + i + SS_; if (gy >= HW_) gy -= HW_;
        int gx = wx * 7 + j + SS_; if (gx >= HW_) gx -= HW_;
        float4 v = *(const float4*)&x[(((size_t)b * HW_ + gy) * HW_ + gx) * 96 + f4 * 4];
        *(ull*)((unsigned short*)(sm + XA_O) + n * 104 + f4 * 4) = cvt4_f16(v);
    }
    {
        const uint4* sq = (const uint4*)g_wqkv;
        uint4* dq = (uint4*)(sm + WQ_O);
        for (int u = tid; u < 3552; u += 256) dq[u] = sq[u];
    }
    __syncthreads();   // bar A

    const uint32_t sb = smem_u32(sm);
    const int r0 = band * 16 + grp, r1 = r0 + 8;

    // ---- phase 2: QKV gemm [64 x 288], warp = (band, nh) does [16 x 144] ----
    {
        const uint32_t axA = sb + XA_O + (uint32_t)(band * 16 + (lane & 15)) * 208
                           + ((lane & 16) ? 16u : 0u);
        const uint32_t bqA = sb + WQ_O + (uint32_t)(lane & 15) * 592
                           + ((lane & 16) ? 16u : 0u) + (uint32_t)nh * 288;
        float acc[18][4] = {};
        #pragma unroll
        for (int ks = 0; ks < 6; ks++) {
            uint32_t af[4];
            LDSM4(af, axA + ks * 32);
            #pragma unroll
            for (int g = 0; g < 9; g++) {
                uint32_t bf[4];
                LDSM4T(bf, bqA + (uint32_t)(ks * 16 * 592 + g * 32));
                mma_f16(acc[2 * g],     af, bf);
                mma_f16(acc[2 * g + 1], af, bf + 2);
            }
        }
        __syncthreads();   // bar B (Wqkv reads done; P/Wproj may overlay next)
        #pragma unroll
        for (int t = 0; t < 18; t++) {
            int col = nh * 144 + t * 8 + tig * 2;       // 0..287
            int strip = (col * 21846) >> 21;            // col / 96
            int rem = col - strip * 96;
            float2 bv = __ldg((const float2*)&qkv_b[col]);
            float sc = (strip == 0) ? 0.17677669529663687f : 1.0f;
            int tb = (strip == 0) ? Q_O : (strip == 1) ? K_O : V_O;
            unsigned short* T = (unsigned short*)(sm + tb);
            *(uint32_t*)&T[r0 * 104 + rem] =
                pack_f16x2((acc[t][0] + bv.x) * sc, (acc[t][1] + bv.y) * sc);
            *(uint32_t*)&T[r1 * 104 + rem] =
                pack_f16x2((acc[t][2] + bv.x) * sc, (acc[t][3] + bv.y) * sc);
        }
    }
    __syncthreads();   // bar C (Q/K/V ready)

    // ---- phase 3: Wproj fill + S (12 tiles [16x64]) + register softmax -> P ----
    {
        const uint4* sp = (const uint4*)g_wproj;
        uint4* dp = (uint4*)(sm + WP_O);
        for (int u = tid; u < 1248; u += 256) dp[u] = sp[u];
    }
    #pragma unroll
    for (int rep = 0; rep < 2; rep++) {
        int t = wrp + rep * 8;
        if (t >= 12) break;
        const int head = t >> 2, tband = t & 3;
        const int tr0 = tband * 16 + grp, tr1 = tr0 + 8;
        const uint32_t qA = sb + Q_O + (uint32_t)(tband * 16 + (lane & 15)) * 208
                          + (uint32_t)head * 64 + ((lane & 16) ? 16u : 0u);
        const uint32_t kA = sb + K_O + (uint32_t)((lane & 7) + ((lane & 16) ? 8 : 0)) * 208
                          + (uint32_t)head * 64 + ((lane & 8) ? 16u : 0u);
        float sacc[8][4] = {};
        #pragma unroll
        for (int ks = 0; ks < 2; ks++) {
            uint32_t qf[4];
            LDSM4(qf, qA + ks * 32);
            #pragma unroll
            for (int p = 0; p < 4; p++) {
                uint32_t kf[4];
                LDSM4(kf, kA + (uint32_t)(p * 16 * 208 + ks * 32));
                mma_f16(sacc[2 * p],     qf, kf);
                mma_f16(sacc[2 * p + 1], qf, kf + 2);
            }
        }
        // register softmax: rows tr0 (regs 0/1), tr1 (regs 2/3)
        unsigned short* PT = (unsigned short*)(sm + P_O + head * 9216);
        #pragma unroll
        for (int half = 0; half < 2; half++) {
            const int e0 = half * 2;
            const int row = half ? tr1 : tr0;
            const int c1 = code[row];
            const int i1 = row / 7, j1 = row % 7;
            float mx = -1e30f;
            #pragma unroll
            for (int nt = 0; nt < 8; nt++) {
                #pragma unroll
                for (int e = 0; e < 2; e++) {
                    int m = nt * 8 + tig * 2 + e;
                    float v = sacc[nt][e0 + e];
                    if (m < N_ && code[m] == c1 && row < N_) {
                        float bi = __ldg(&bias_table[
                            ((i1 - m / 7 + 6) * 13 + (j1 - m % 7 + 6)) * NH_ + head]);
                        v += bi;
                    } else v = -1e9f;
                    sacc[nt][e0 + e] = v;
                    mx = fmaxf(mx, v);
                }
            }
            mx = fmaxf(mx, __shfl_xor_sync(0xffffffffu, mx, 1));
            mx = fmaxf(mx, __shfl_xor_sync(0xffffffffu, mx, 2));
            float sum = 0.0f;
            #pragma unroll
            for (int nt = 0; nt < 8; nt++) {
                #pragma unroll
                for (int e = 0; e < 2; e++) {
                    float ex = __expf(sacc[nt][e0 + e] - mx);
                    sacc[nt][e0 + e] = ex;
                    sum += ex;
                }
            }
            sum += __shfl_xor_sync(0xffffffffu, sum, 1);
            sum += __shfl_xor_sync(0xffffffffu, sum, 2);
            float inv = 1.0f / sum;
            #pragma unroll
            for (int nt = 0; nt < 8; nt++) {
                *(uint32_t*)&PT[row * 72 + nt * 8 + tig * 2] =
                    pack_f16x2(sacc[nt][e0] * inv, sacc[nt][e0 + 1] * inv);
            }
        }
    }
    __syncthreads();   // bar D (P + Wproj ready)

    // ---- phase 4: PV (12 tiles [16x32]) -> O (overlays XA) ----
    #pragma unroll
    for (int rep = 0; rep < 2; rep++) {
        int t = wrp + rep * 8;
        if (t >= 12) break;
        const int head = t >> 2, tband = t & 3;
        const int tr0 = tband * 16 + grp, tr1 = tr0 + 8;
        const uint32_t pA = sb + P_O + (uint32_t)(head * 9216)
                          + (uint32_t)(tband * 16 + (lane & 15)) * 144
                          + ((lane & 16) ? 16u : 0u);
        const uint32_t vA = sb + V_O + (uint32_t)(lane & 15) * 208
                          + (uint32_t)head * 64 + ((lane & 16) ? 16u : 0u);
        float oacc[4][4] = {};
        #pragma unroll
        for (int ks = 0; ks < 4; ks++) {
            uint32_t pf[4];
            LDSM4(pf, pA + ks * 32);
            #pragma unroll
            for (int g = 0; g < 2; g++) {
                uint32_t vf[4];
                LDSM4T(vf, vA + (uint32_t)(ks * 16 * 208 + g * 32));
                mma_f16(oacc[2 * g],     pf, vf);
                mma_f16(oacc[2 * g + 1], pf, vf + 2);
            }
        }
        unsigned short* OT = (unsigned short*)(sm + O_O);
        #pragma unroll
        for (int nt = 0; nt < 4; nt++) {
            int col = head * 32 + nt * 8 + tig * 2;
            *(uint32_t*)&OT[tr0 * 104 + col] = pack_f16x2(oacc[nt][0], oacc[nt][1]);
            *(uint32_t*)&OT[tr1 * 104 + col] = pack_f16x2(oacc[nt][2], oacc[nt][3]);
        }
    }
    __syncthreads();   // bar E (O ready)

    // ---- phase 5: proj [64x96] K=96, warp = (band, nh) does [16x48]; scatter ----
    {
        const uint32_t oA = sb + O_O + (uint32_t)(band * 16 + (lane & 15)) * 208
                          + ((lane & 16) ? 16u : 0u);
        const uint32_t wpA = sb + WP_O + (uint32_t)(lane & 15) * 208
                           + ((lane & 16) ? 16u : 0u) + (uint32_t)nh * 96;
        float pacc[6][4] = {};
        #pragma unroll
        for (int ks = 0; ks < 6; ks++) {
            uint32_t of[4];
            LDSM4(of, oA + ks * 32);
            #pragma unroll
            for (int g = 0; g < 3; g++) {
                uint32_t wf[4];
                LDSM4T(wf, wpA + (uint32_t)(ks * 16 * 208 + g * 32));
                mma_f16(pacc[2 * g],     of, wf);
                mma_f16(pacc[2 * g + 1], of, wf + 2);
            }
        }
        #pragma unroll
        for (int t = 0; t < 6; t++) {
            int col = nh * 48 + t * 8 + tig * 2;
            float2 pb = __ldg((const float2*)&proj_b[col]);
            if (r0 < N_) {
                float2 o; o.x = pacc[t][0] + pb.x; o.y = pacc[t][1] + pb.y;
                *(float2*)&out[(size_t)tokv[r0] * 96 + col] = o;
            }
            if (r1 < N_) {
                float2 o; o.x = pacc[t][2] + pb.x; o.y = pacc[t][3] + pb.y;
                *(float2*)&out[(size_t)tokv[r1] * 96 + col] = o;
            }
        }
    }
}

// ---------------------------------------------------------------------------
extern "C" void kernel_launch(void* const* d_in, const int* in_sizes, int n_in,
                              void* d_out, int out_size)
{
    (void)in_sizes; (void)n_in; (void)out_size;
    const float* x          = (const float*)d_in[0];
    const float* qkv_w      = (const float*)d_in[1];
    const float* qkv_b      = (const float*)d_in[2];
    const float* proj_w     = (const float*)d_in[3];
    const float* proj_b     = (const float*)d_in[4];
    const float* bias_table = (const float*)d_in[5];
    float* out = (float*)d_out;

    static bool attr_done = false;
    if (!attr_done) {
        cudaFuncSetAttribute(k_fused, cudaFuncAttributeMaxDynamicSharedMemorySize, SMEM_FUSED);
        attr_done = true;
    }

    k_prepack<<<1, 256>>>(qkv_w, proj_w);
    k_fused<<<BNW, 256, SMEM_FUSED>>>(x, qkv_b, proj_b, bias_table, out);
}